// round 8
// baseline (speedup 1.0000x reference)
#include <cuda_runtime.h>
#include <cuda_bf16.h>
#include <cstdint>
#include <cstddef>

#define B_    4
#define S_    512
#define D_    768
#define H_    12
#define HD_   64
#define NRELV 101
#define EROWS 112
#define XN    (B_*S_*D_)
#define WN    (D_*D_)

#define BM    128
#define BN    128
#define BK    32
#define LDSB  40           // bf16 stride (80B) -> ldmatrix conflict-free
#define GSTAGE 40960       // bytes per gemm pipeline stage

// ---------------- scratch ------------------------------------------------------
__device__ __nv_bfloat16 g_qkhi[(size_t)B_*H_*S_*128], g_qklo[(size_t)B_*H_*S_*128];
__device__ __nv_bfloat16 g_vhi[XN], g_vlo[XN];
__device__ __nv_bfloat16 g_xhi[3*XN], g_xlo[3*XN];
__device__ __nv_bfloat16 g_whi[4*WN], g_wlo[4*WN];
__device__ __nv_bfloat16 g_chi[XN], g_clo[XN];
__device__ __nv_bfloat16 g_ehi[EROWS*128], g_elo[EROWS*128];
__device__ float   g_bias[(size_t)B_*H_*S_*NRELV];
__device__ uint8_t g_rel8[(size_t)B_*S_*S_];
__device__ int     g_arc_is64;

// ---------------- helpers ------------------------------------------------------
__device__ __forceinline__ void split2(float a, float b, uint32_t& hi, uint32_t& lo)
{
    __nv_bfloat16 h0 = __float2bfloat16(a);
    __nv_bfloat16 h1 = __float2bfloat16(b);
    __nv_bfloat16 l0 = __float2bfloat16(a - __bfloat162float(h0));
    __nv_bfloat16 l1 = __float2bfloat16(b - __bfloat162float(h1));
    hi = (uint32_t)*(unsigned short*)&h0 | ((uint32_t)*(unsigned short*)&h1 << 16);
    lo = (uint32_t)*(unsigned short*)&l0 | ((uint32_t)*(unsigned short*)&l1 << 16);
}

__device__ __forceinline__ void ldsm_x4(uint32_t addr, uint32_t& r0, uint32_t& r1,
                                        uint32_t& r2, uint32_t& r3)
{
    asm volatile("ldmatrix.sync.aligned.m8n8.x4.shared.b16 {%0,%1,%2,%3}, [%4];"
                 : "=r"(r0), "=r"(r1), "=r"(r2), "=r"(r3) : "r"(addr));
}

__device__ __forceinline__ void ldsm_x2_trans(uint32_t addr, uint32_t& r0, uint32_t& r1)
{
    asm volatile("ldmatrix.sync.aligned.m8n8.x2.trans.shared.b16 {%0,%1}, [%2];"
                 : "=r"(r0), "=r"(r1) : "r"(addr));
}

__device__ __forceinline__ void mma16816(float* c, const uint32_t* a,
                                         uint32_t b0, uint32_t b1)
{
    asm volatile(
        "mma.sync.aligned.m16n8k16.row.col.f32.bf16.bf16.f32 "
        "{%0,%1,%2,%3}, {%4,%5,%6,%7}, {%8,%9}, {%0,%1,%2,%3};"
        : "+f"(c[0]), "+f"(c[1]), "+f"(c[2]), "+f"(c[3])
        : "r"(a[0]), "r"(a[1]), "r"(a[2]), "r"(a[3]), "r"(b0), "r"(b1));
}

__device__ __forceinline__ void cp16(uint32_t dst, const void* src)
{
    asm volatile("cp.async.ca.shared.global [%0], [%1], 16;" :: "r"(dst), "l"(src));
}

// ---------------- graph_arc dtype detection ------------------------------------
__global__ void detect_kernel(const int* __restrict__ arc32)
{
    __shared__ int cnt;
    if (threadIdx.x == 0) cnt = 0;
    __syncthreads();
    int local = 0;
    for (int i = threadIdx.x; i < 1024; i += blockDim.x)
        if (arc32[2*i + 1] != 0) local++;
    if (local) atomicAdd(&cnt, local);
    __syncthreads();
    if (threadIdx.x == 0) g_arc_is64 = (cnt == 0) ? 1 : 0;
}

// arc (int32 or int64) -> uint8 relation table
__global__ void __launch_bounds__(256)
rel8_kernel(const void* __restrict__ arc)
{
    const int is64 = g_arc_is64;
    const size_t i = ((size_t)blockIdx.x * 256 + threadIdx.x) * 4;
    if (i >= (size_t)B_*S_*S_) return;
    uchar4 r;
    if (is64) {
        const long long* a = (const long long*)arc + i;
        r = make_uchar4((uint8_t)a[0], (uint8_t)a[1], (uint8_t)a[2], (uint8_t)a[3]);
    } else {
        const int* a = (const int*)arc + i;
        r = make_uchar4((uint8_t)a[0], (uint8_t)a[1], (uint8_t)a[2], (uint8_t)a[3]);
    }
    *(uchar4*)&g_rel8[i] = r;
}

// ---------------- prepass: fp32 -> bf16 hi/lo split -----------------------------
struct SplitArgs {
    const float*   src[7];
    __nv_bfloat16* hi[7];
    __nv_bfloat16* lo[7];
    int            n[7];
};

__global__ void __launch_bounds__(256)
split_kernel(SplitArgs a)
{
    const int w = blockIdx.y;
    const int n = a.n[w];
    const int i = (blockIdx.x * 256 + threadIdx.x) * 4;
    if (i >= n) return;
    float4 v = *(const float4*)(a.src[w] + i);
    uint32_t h0, l0, h1, l1;
    split2(v.x, v.y, h0, l0);
    split2(v.z, v.w, h1, l1);
    *(uint2*)(a.hi[w] + i) = make_uint2(h0, h1);
    *(uint2*)(a.lo[w] + i) = make_uint2(l0, l1);
}

__global__ void __launch_bounds__(256)
ebuild_kernel(const float* __restrict__ Ek, const float* __restrict__ Eq)
{
    int idx = blockIdx.x * 256 + threadIdx.x;
    if (idx >= EROWS*128) return;
    int row = idx >> 7, col = idx & 127;
    float v = 0.f;
    if (row < NRELV) v = (col < 64) ? Ek[row*64 + col] : Eq[row*64 + col - 64];
    __nv_bfloat16 hv = __float2bfloat16(v);
    __nv_bfloat16 lv = __float2bfloat16(v - __bfloat162float(hv));
    g_ehi[idx] = hv;
    g_elo[idx] = lv;
}

// ---------------- tensor-core GEMM, cp.async 2-stage pipeline (round-6) ---------
template<int MODE>
__global__ void __launch_bounds__(256, 2)
mma_gemm_kernel(const float* __restrict__ bias0, const float* __restrict__ bias1,
                const float* __restrict__ bias2, float* __restrict__ out1)
{
    extern __shared__ char gsm[];
    const uint32_t smemBase = (uint32_t)__cvta_generic_to_shared(gsm);

    const int z = (MODE == 0) ? blockIdx.z : 0;
    const __nv_bfloat16 *Xhi, *Xlo, *Whi, *Wlo;
    const float* bias;
    if (MODE == 0) {
        Xhi = g_xhi + (size_t)z*XN;  Xlo = g_xlo + (size_t)z*XN;
        Whi = g_whi + (size_t)z*WN;  Wlo = g_wlo + (size_t)z*WN;
        bias = (z == 0) ? bias0 : (z == 1) ? bias1 : bias2;
    } else {
        Xhi = g_chi;  Xlo = g_clo;
        Whi = g_whi + (size_t)3*WN;  Wlo = g_wlo + (size_t)3*WN;
        bias = bias0;
    }

    const int tid  = threadIdx.x;
    const int lane = tid & 31;
    const int warp = tid >> 5;
    const int wm   = warp & 3;
    const int wn   = warp >> 2;
    const int m0   = blockIdx.y * BM;
    const int n0   = blockIdx.x * BN;

    float acc[2][8][4];
    #pragma unroll
    for (int mt = 0; mt < 2; mt++)
        #pragma unroll
        for (int nt = 0; nt < 8; nt++)
            #pragma unroll
            for (int j = 0; j < 4; j++) acc[mt][nt][j] = 0.f;

    const int mat = lane >> 3, mr = lane & 7;
    const uint32_t aOffHi = (uint32_t)((wm*32 + (mat & 1)*8 + mr)*80 + ((mat >> 1)*8)*2);
    const uint32_t bOffHi = 20480u + (uint32_t)((wn*64 + (mat >> 1)*8 + mr)*80 + ((mat & 1)*8)*2);

    const int ldrow = tid >> 1;
    const int ldq   = (tid & 1) * 2;
    const uint32_t xDst = (uint32_t)(ldrow*80 + ldq*16);
    const uint32_t wDst = 20480u + xDst;

    #pragma unroll
    for (int u = 0; u < 2; u++) {
        const size_t xo = (size_t)(m0 + ldrow)*D_ + (ldq + u)*8;
        const size_t wo = (size_t)(n0 + ldrow)*D_ + (ldq + u)*8;
        cp16(smemBase + xDst + u*16,          Xhi + xo);
        cp16(smemBase + 10240 + xDst + u*16,  Xlo + xo);
        cp16(smemBase + wDst + u*16,          Whi + wo);
        cp16(smemBase + 10240 + wDst + u*16,  Wlo + wo);
    }
    asm volatile("cp.async.commit_group;");

    const int NK = D_ / BK;
    for (int kt = 0; kt < NK; kt++) {
        asm volatile("cp.async.wait_group 0;");
        __syncthreads();

        if (kt + 1 < NK) {
            const uint32_t sb2 = smemBase + (uint32_t)(((kt + 1) & 1) * GSTAGE);
            const int k0 = (kt + 1) * BK;
            #pragma unroll
            for (int u = 0; u < 2; u++) {
                const size_t xo = (size_t)(m0 + ldrow)*D_ + k0 + (ldq + u)*8;
                const size_t wo = (size_t)(n0 + ldrow)*D_ + k0 + (ldq + u)*8;
                cp16(sb2 + xDst + u*16,          Xhi + xo);
                cp16(sb2 + 10240 + xDst + u*16,  Xlo + xo);
                cp16(sb2 + wDst + u*16,          Whi + wo);
                cp16(sb2 + 10240 + wDst + u*16,  Wlo + wo);
            }
        }
        asm volatile("cp.async.commit_group;");

        const uint32_t sb = smemBase + (uint32_t)((kt & 1) * GSTAGE);
        #pragma unroll
        for (int ks = 0; ks < 2; ks++) {
            const uint32_t ko = ks * 32;
            uint32_t ah[2][4], al[2][4];
            #pragma unroll
            for (int mt = 0; mt < 2; mt++) {
                const uint32_t mo = mt * 1280;
                ldsm_x4(sb + aOffHi + mo + ko,          ah[mt][0], ah[mt][1], ah[mt][2], ah[mt][3]);
                ldsm_x4(sb + aOffHi + 10240 + mo + ko,  al[mt][0], al[mt][1], al[mt][2], al[mt][3]);
            }
            #pragma unroll
            for (int pr = 0; pr < 4; pr++) {
                const uint32_t po = pr * 1280;
                uint32_t bh[4], bl[4];
                ldsm_x4(sb + bOffHi + po + ko,          bh[0], bh[1], bh[2], bh[3]);
                ldsm_x4(sb + bOffHi + 10240 + po + ko,  bl[0], bl[1], bl[2], bl[3]);
                #pragma unroll
                for (int h2 = 0; h2 < 2; h2++) {
                    const int nt = pr*2 + h2;
                    #pragma unroll
                    for (int mt = 0; mt < 2; mt++) {
                        mma16816(acc[mt][nt], ah[mt], bh[h2*2], bh[h2*2+1]);
                        mma16816(acc[mt][nt], ah[mt], bl[h2*2], bl[h2*2+1]);
                        mma16816(acc[mt][nt], al[mt], bh[h2*2], bh[h2*2+1]);
                    }
                }
            }
        }
    }

    const int gid = lane >> 2, tig = lane & 3;
    #pragma unroll
    for (int mt = 0; mt < 2; mt++) {
        const int rbase = m0 + wm*32 + mt*16 + gid;
        #pragma unroll
        for (int nt = 0; nt < 8; nt++) {
            const int col = n0 + wn*64 + nt*8 + tig*2;
            const float b0v = bias[col], b1v = bias[col+1];
            float v00 = acc[mt][nt][0] + b0v;
            float v01 = acc[mt][nt][1] + b1v;
            float v10 = acc[mt][nt][2] + b0v;
            float v11 = acc[mt][nt][3] + b1v;
            if (MODE == 0) {
                const int hh = col >> 6, e = col & 63;
                #pragma unroll
                for (int half = 0; half < 2; half++) {
                    const int r = rbase + half*8;
                    const int b = r >> 9, s = r & (S_-1);
                    const size_t rowb = (size_t)(b*H_ + hh)*S_ + s;
                    const float va = half ? v10 : v00;
                    const float vb = half ? v11 : v01;
                    uint32_t hi, lo; split2(va, vb, hi, lo);
                    if (z == 0) {
                        *(uint32_t*)&g_qkhi[rowb*128 + e] = hi;
                        *(uint32_t*)&g_qklo[rowb*128 + e] = lo;
                    } else if (z == 1) {
                        *(uint32_t*)&g_qkhi[rowb*128 + 64 + e] = hi;
                        *(uint32_t*)&g_qklo[rowb*128 + 64 + e] = lo;
                    } else {
                        *(uint32_t*)&g_vhi[rowb*64 + e] = hi;
                        *(uint32_t*)&g_vlo[rowb*64 + e] = lo;
                    }
                }
            } else {
                out1[(size_t)rbase*D_ + col]       = v00;
                out1[(size_t)rbase*D_ + col + 1]   = v01;
                out1[(size_t)(rbase+8)*D_ + col]   = v10;
                out1[(size_t)(rbase+8)*D_ + col+1] = v11;
            }
        }
    }
}

// ---------------- bias table via tensor cores -----------------------------------
__global__ void __launch_bounds__(256, 1)
bias_mma_kernel()
{
    __shared__ __nv_bfloat16 sAhi[128][LDSB], sAlo[128][LDSB];
    __shared__ __nv_bfloat16 sBhi[EROWS][LDSB], sBlo[EROWS][LDSB];

    const int rt = blockIdx.x;
    const int h  = blockIdx.y, b = blockIdx.z;
    const size_t bh = (size_t)b*H_ + h;
    const size_t abase = (bh*S_ + rt*128) * 128;

    const int tid  = threadIdx.x;
    const int lane = tid & 31;
    const int warp = tid >> 5;

    float acc[14][4];
    #pragma unroll
    for (int nt = 0; nt < 14; nt++)
        #pragma unroll
        for (int j = 0; j < 4; j++) acc[nt][j] = 0.f;

    const int mat = lane >> 3, mr = lane & 7;
    const int a_row = (mat & 1) * 8 + mr;
    const int a_k   = (mat >> 1) * 8;
    const uint32_t aHi = (uint32_t)__cvta_generic_to_shared(&sAhi[warp*16 + a_row][a_k]);
    const uint32_t aLo = (uint32_t)__cvta_generic_to_shared(&sAlo[warp*16 + a_row][a_k]);
    const int b_row = (mat >> 1) * 8 + mr;
    const int b_k   = (mat & 1) * 8;
    const uint32_t bHi = (uint32_t)__cvta_generic_to_shared(&sBhi[b_row][b_k]);
    const uint32_t bLo = (uint32_t)__cvta_generic_to_shared(&sBlo[b_row][b_k]);

    for (int k0 = 0; k0 < 128; k0 += BK) {
        {
            const int arow = tid >> 1;
            const int acol = (tid & 1) * 16;
            const size_t src = abase + (size_t)arow*128 + k0 + acol;
            uint4 h0 = *(const uint4*)(g_qkhi + src);
            uint4 h1 = *(const uint4*)(g_qkhi + src + 8);
            uint4 l0 = *(const uint4*)(g_qklo + src);
            uint4 l1 = *(const uint4*)(g_qklo + src + 8);
            __syncthreads();
            *(uint4*)&sAhi[arow][acol]     = h0;
            *(uint4*)&sAhi[arow][acol + 8] = h1;
            *(uint4*)&sAlo[arow][acol]     = l0;
            *(uint4*)&sAlo[arow][acol + 8] = l1;
        }
        if (tid < EROWS*2) {
            const int brow = tid >> 1;
            const int bcol = (tid & 1) * 16;
            const size_t src = (size_t)brow*128 + k0 + bcol;
            *(uint4*)&sBhi[brow][bcol]     = *(const uint4*)(g_ehi + src);
            *(uint4*)&sBhi[brow][bcol + 8] = *(const uint4*)(g_ehi + src + 8);
            *(uint4*)&sBlo[brow][bcol]     = *(const uint4*)(g_elo + src);
            *(uint4*)&sBlo[brow][bcol + 8] = *(const uint4*)(g_elo + src + 8);
        }
        __syncthreads();

        #pragma unroll
        for (int ks = 0; ks < 2; ks++) {
            const uint32_t ko = ks * 32;
            uint32_t ah[4], al[4];
            ldsm_x4(aHi + ko, ah[0], ah[1], ah[2], ah[3]);
            ldsm_x4(aLo + ko, al[0], al[1], al[2], al[3]);
            #pragma unroll
            for (int pr = 0; pr < 7; pr++) {
                const uint32_t po = pr * (16 * LDSB * 2);
                uint32_t bhf[4], blf[4];
                ldsm_x4(bHi + po + ko, bhf[0], bhf[1], bhf[2], bhf[3]);
                ldsm_x4(bLo + po + ko, blf[0], blf[1], blf[2], blf[3]);
                #pragma unroll
                for (int h2 = 0; h2 < 2; h2++) {
                    const int nt = pr*2 + h2;
                    mma16816(acc[nt], ah, bhf[h2*2], bhf[h2*2+1]);
                    mma16816(acc[nt], ah, blf[h2*2], blf[h2*2+1]);
                    mma16816(acc[nt], al, bhf[h2*2], bhf[h2*2+1]);
                }
            }
        }
        __syncthreads();
    }

    const int gid = lane >> 2, tig = lane & 3;
    const int row0 = rt*128 + warp*16 + gid;
    #pragma unroll
    for (int nt = 0; nt < 14; nt++) {
        const int col = nt*8 + tig*2;
        #pragma unroll
        for (int half = 0; half < 2; half++) {
            const int row = row0 + half*8;
            const size_t o = (bh*S_ + row)*NRELV;
            const float v0 = acc[nt][half*2];
            const float v1 = acc[nt][half*2+1];
            if (col < NRELV)     g_bias[o + col]     = v0;
            if (col + 1 < NRELV) g_bias[o + col + 1] = v1;
        }
    }
}

// ---------------- fused attention: QT=16, 256 thr, 2 CTAs/SM --------------------
#define QT    16
#define SSTR  520
#define OFF_SS    0                       // 16*520*4 = 33280
#define OFF_KHI   33280                   // 128*72*2 = 18432
#define OFF_KLO   51712                   // -> 70144
#define OFF_EV    33280                   // Ev fp32 101*64 (reuses K region)
#define OFF_SB    70144                   // 16*101*4 = 6464
#define OFF_SW    76608                   // 6464
#define OFF_SZ    83072                   // 64
#define OFF_MASK  83136                   // 2048
#define SMEM_ATTN 85184

__global__ void __launch_bounds__(256, 2)
attn_kernel(const int* __restrict__ mask, const float* __restrict__ Ev)
{
    extern __shared__ char smraw[];
    float* sS    = (float*)(smraw + OFF_SS);
    __nv_bfloat16* sKhi = (__nv_bfloat16*)(smraw + OFF_KHI);
    __nv_bfloat16* sKlo = (__nv_bfloat16*)(smraw + OFF_KLO);
    float* sEv   = (float*)(smraw + OFF_EV);
    float* sB    = (float*)(smraw + OFF_SB);
    float* sW    = (float*)(smraw + OFF_SW);
    float* sZ    = (float*)(smraw + OFF_SZ);
    int*   sMask = (int*)  (smraw + OFF_MASK);

    const int qt = blockIdx.x, h = blockIdx.y, b = blockIdx.z;
    const int i0 = qt * QT;
    const int tid  = threadIdx.x;
    const int lane = tid & 31;
    const int warp = tid >> 5;
    const size_t bh    = (size_t)b*H_ + h;
    const size_t qrow0 = bh*S_ + i0;
    const size_t krow0 = bh*S_;
    const size_t vbase = bh*S_*HD_;

    for (int i = tid; i < QT*NRELV; i += 256) {
        sB[i] = g_bias[qrow0*NRELV + i];
        sW[i] = 0.f;
    }
    for (int i = tid; i < S_; i += 256) sMask[i] = mask[b*S_ + i];
    __syncthreads();

    // ---- Q A-fragments from pre-split global ----
    uint32_t qah[4][4], qal[4][4];
    {
        const int qr = lane >> 2;
        const int qc = (lane & 3) * 2;
        #pragma unroll
        for (int kk = 0; kk < 4; kk++) {
            const size_t r0o = (qrow0 + qr)*128     + kk*16 + qc;
            const size_t r1o = (qrow0 + qr + 8)*128 + kk*16 + qc;
            qah[kk][0] = *(const uint32_t*)&g_qkhi[r0o];
            qah[kk][1] = *(const uint32_t*)&g_qkhi[r1o];
            qah[kk][2] = *(const uint32_t*)&g_qkhi[r0o + 8];
            qah[kk][3] = *(const uint32_t*)&g_qkhi[r1o + 8];
            qal[kk][0] = *(const uint32_t*)&g_qklo[r0o];
            qal[kk][1] = *(const uint32_t*)&g_qklo[r1o];
            qal[kk][2] = *(const uint32_t*)&g_qklo[r0o + 8];
            qal[kk][3] = *(const uint32_t*)&g_qklo[r1o + 8];
        }
    }

    // tile copy mapping: 2 threads/row, each a contiguous 32-elem half
    const int copyrow = tid >> 1;
    const int chalf   = (tid & 1) * 32;

    // ---- pass 1: S = Q K^T via mma ----
    for (int jt = 0; jt < 4; jt++) {
        const int j0 = jt * 128;
        {
            const size_t src = (krow0 + j0 + copyrow)*128 + 64 + chalf;
            #pragma unroll
            for (int u = 0; u < 4; u++) {
                *(uint4*)&sKhi[copyrow*72 + chalf + u*8] = *(const uint4*)(g_qkhi + src + u*8);
                *(uint4*)&sKlo[copyrow*72 + chalf + u*8] = *(const uint4*)(g_qklo + src + u*8);
            }
        }
        __syncthreads();

        float c[2][4] = {{0,0,0,0},{0,0,0,0}};
        const int nw = warp * 16;
        #pragma unroll
        for (int kk = 0; kk < 4; kk++) {
            #pragma unroll
            for (int nt = 0; nt < 2; nt++) {
                const int j = nw + nt*8 + (lane >> 2);
                const int d = kk*16 + (lane & 3)*2;
                uint32_t bh0 = *(uint32_t*)&sKhi[j*72 + d];
                uint32_t bh1 = *(uint32_t*)&sKhi[j*72 + d + 8];
                uint32_t bl0 = *(uint32_t*)&sKlo[j*72 + d];
                uint32_t bl1 = *(uint32_t*)&sKlo[j*72 + d + 8];
                mma16816(c[nt], qah[kk], bh0, bh1);
                mma16816(c[nt], qah[kk], bl0, bl1);
                mma16816(c[nt], qal[kk], bh0, bh1);
            }
        }
        #pragma unroll
        for (int nt = 0; nt < 2; nt++) {
            const int col = j0 + nw + nt*8 + 2*(lane & 3);
            const int r   = lane >> 2;
            *(float2*)&sS[r*SSTR + col]     = make_float2(c[nt][0], c[nt][1]);
            *(float2*)&sS[(r+8)*SSTR + col] = make_float2(c[nt][2], c[nt][3]);
        }
        __syncthreads();
    }

    // ---- relation bias + scale + mask (rel from precomputed u8 table) ----
    const size_t arcbase = ((size_t)b*S_ + i0)*S_;
    for (int idx4 = tid; idx4 < QT*S_/4; idx4 += 256) {
        const int idx = idx4 * 4;
        const int i = idx >> 9, j = idx & (S_-1);
        uchar4 r4 = *(const uchar4*)&g_rel8[arcbase + (size_t)i*S_ + j];
        const float* brow = &sB[i*NRELV];
        float4 s4 = *(float4*)&sS[i*SSTR + j];
        s4.x = (s4.x + brow[r4.x]) * 0.125f; if (sMask[j]     == 0) s4.x = -1e30f;
        s4.y = (s4.y + brow[r4.y]) * 0.125f; if (sMask[j + 1] == 0) s4.y = -1e30f;
        s4.z = (s4.z + brow[r4.z]) * 0.125f; if (sMask[j + 2] == 0) s4.z = -1e30f;
        s4.w = (s4.w + brow[r4.w]) * 0.125f; if (sMask[j + 3] == 0) s4.w = -1e30f;
        *(float4*)&sS[i*SSTR + j] = s4;
    }
    __syncthreads();

    // ---- softmax (unnormalized exp; Z per row) ----
    #pragma unroll
    for (int rr = 0; rr < 2; rr++) {
        int row = warp*2 + rr;
        float m = -3.4e38f;
        for (int j = lane; j < S_; j += 32) m = fmaxf(m, sS[row*SSTR + j]);
        #pragma unroll
        for (int o = 16; o; o >>= 1) m = fmaxf(m, __shfl_xor_sync(0xffffffffu, m, o));
        float z = 0.f;
        for (int j = lane; j < S_; j += 32) {
            float p = __expf(sS[row*SSTR + j] - m);
            sS[row*SSTR + j] = p;
            z += p;
        }
        #pragma unroll
        for (int o = 16; o; o >>= 1) z += __shfl_xor_sync(0xffffffffu, z, o);
        if (lane == 0) sZ[row] = z;
    }
    __syncthreads();

    // ---- relation binning (rel from u8 table) ----
    for (int idx4 = tid; idx4 < QT*S_/4; idx4 += 256) {
        const int idx = idx4 * 4;
        const int i = idx >> 9, j = idx & (S_-1);
        uchar4 r4 = *(const uchar4*)&g_rel8[arcbase + (size_t)i*S_ + j];
        float4 p4 = *(float4*)&sS[i*SSTR + j];
        float* wrow = &sW[i*NRELV];
        atomicAdd(&wrow[r4.x], p4.x);
        atomicAdd(&wrow[r4.y], p4.y);
        atomicAdd(&wrow[r4.z], p4.z);
        atomicAdd(&wrow[r4.w], p4.w);
    }
    __syncthreads();

    // ---- pass 2: ctx = P V via mma ----
    float c2[8][4];
    #pragma unroll
    for (int nt = 0; nt < 8; nt++)
        #pragma unroll
        for (int j = 0; j < 4; j++) c2[nt][j] = 0.f;

    const uint32_t vhiBase = (uint32_t)__cvta_generic_to_shared(sKhi);
    const uint32_t vloBase = (uint32_t)__cvta_generic_to_shared(sKlo);
    for (int jt = 0; jt < 4; jt++) {
        {
            const size_t src = vbase + (size_t)(jt*128 + copyrow)*HD_ + chalf;
            #pragma unroll
            for (int u = 0; u < 4; u++) {
                *(uint4*)&sKhi[copyrow*72 + chalf + u*8] = *(const uint4*)(g_vhi + src + u*8);
                *(uint4*)&sKlo[copyrow*72 + chalf + u*8] = *(const uint4*)(g_vlo + src + u*8);
            }
        }
        __syncthreads();

        const int jb = jt*128 + warp*16;
        uint32_t pah[4], pal[4];
        {
            const int pr = lane >> 2;
            const int pc = (lane & 3) * 2;
            float2 x0 = *(float2*)&sS[pr*SSTR     + jb + pc];
            float2 x1 = *(float2*)&sS[(pr+8)*SSTR + jb + pc];
            float2 x2 = *(float2*)&sS[pr*SSTR     + jb + pc + 8];
            float2 x3 = *(float2*)&sS[(pr+8)*SSTR + jb + pc + 8];
            split2(x0.x, x0.y, pah[0], pal[0]);
            split2(x1.x, x1.y, pah[1], pal[1]);
            split2(x2.x, x2.y, pah[2], pal[2]);
            split2(x3.x, x3.y, pah[3], pal[3]);
        }
        const uint32_t rowoff = (uint32_t)(warp*16 + (lane & 15)) * 144;
        #pragma unroll
        for (int nt = 0; nt < 8; nt++) {
            uint32_t bh0, bh1, bl0, bl1;
            ldsm_x2_trans(vhiBase + rowoff + nt*16, bh0, bh1);
            ldsm_x2_trans(vloBase + rowoff + nt*16, bl0, bl1);
            mma16816(c2[nt], pah, bh0, bh1);
            mma16816(c2[nt], pah, bl0, bl1);
            mma16816(c2[nt], pal, bh0, bh1);
        }
        __syncthreads();
    }

    // ---- cross-warp reduction of PV partials (reuse sS) + load Ev ----
    {
        float* red = sS;
        const int r = lane >> 2;
        #pragma unroll
        for (int nt = 0; nt < 8; nt++) {
            const int col = nt*8 + 2*(lane & 3);
            red[warp*1024 + r*64 + col]       = c2[nt][0];
            red[warp*1024 + r*64 + col + 1]   = c2[nt][1];
            red[warp*1024 + (r+8)*64 + col]   = c2[nt][2];
            red[warp*1024 + (r+8)*64 + col+1] = c2[nt][3];
        }
    }
    for (int i = tid; i < NRELV*HD_; i += 256) sEv[i] = Ev[i];
    __syncthreads();

    // ---- final: reduce, + wrel@Ev, /Z, store ctx as bf16 hi/lo ----
    {
        const int row = tid >> 4;            // 0..15
        const int e0  = (tid & 15) * 4;      // 0..60
        float4 acc = make_float4(0,0,0,0);
        #pragma unroll
        for (int w = 0; w < 8; w++) {
            float4 p = *(float4*)&sS[w*1024 + row*64 + e0];
            acc.x += p.x; acc.y += p.y; acc.z += p.z; acc.w += p.w;
        }
        const float* wrow = &sW[row*NRELV];
        for (int rel = 0; rel < NRELV; rel++) {
            float wv = wrow[rel];
            float4 ev = *(float4*)&sEv[rel*64 + e0];
            acc.x += wv*ev.x; acc.y += wv*ev.y; acc.z += wv*ev.z; acc.w += wv*ev.w;
        }
        const float rz = 1.f / sZ[row];
        acc.x *= rz; acc.y *= rz; acc.z *= rz; acc.w *= rz;

        uint32_t h0, l0, h1, l1;
        split2(acc.x, acc.y, h0, l0);
        split2(acc.z, acc.w, h1, l1);
        const size_t o = ((size_t)(b*S_ + i0 + row))*D_ + h*HD_ + e0;
        *(uint2*)&g_chi[o] = make_uint2(h0, h1);
        *(uint2*)&g_clo[o] = make_uint2(l0, l1);
    }
}

// ---------------- launch --------------------------------------------------------
extern "C" void kernel_launch(void* const* d_in, const int* in_sizes, int n_in,
                              void* d_out, int out_size)
{
    (void)in_sizes; (void)n_in; (void)out_size;
    const float* query = (const float*)d_in[0];
    const float* key_  = (const float*)d_in[1];
    const float* value = (const float*)d_in[2];
    const int*   mask  = (const int*)d_in[3];
    const void*  arc   = d_in[4];
    const float* bq = (const float*)d_in[6];
    const float* bk = (const float*)d_in[8];
    const float* bv = (const float*)d_in[10];
    const float* bo = (const float*)d_in[12];
    const float* Ek = (const float*)d_in[13];
    const float* Eq = (const float*)d_in[14];
    const float* Ev = (const float*)d_in[15];
    float* out = (float*)d_out;

    cudaFuncSetAttribute(attn_kernel, cudaFuncAttributeMaxDynamicSharedMemorySize, SMEM_ATTN);
    cudaFuncSetAttribute(mma_gemm_kernel<0>, cudaFuncAttributeMaxDynamicSharedMemorySize, 2*GSTAGE);
    cudaFuncSetAttribute(mma_gemm_kernel<1>, cudaFuncAttributeMaxDynamicSharedMemorySize, 2*GSTAGE);

    __nv_bfloat16 *xhi, *xlo, *whi, *wlo;
    cudaGetSymbolAddress((void**)&xhi, g_xhi);
    cudaGetSymbolAddress((void**)&xlo, g_xlo);
    cudaGetSymbolAddress((void**)&whi, g_whi);
    cudaGetSymbolAddress((void**)&wlo, g_wlo);

    detect_kernel<<<1, 256>>>((const int*)arc);
    rel8_kernel<<<((B_*S_*S_/4) + 255)/256, 256>>>(arc);

    SplitArgs sa;
    const float* srcs[7] = {query, key_, value,
                            (const float*)d_in[5], (const float*)d_in[7],
                            (const float*)d_in[9], (const float*)d_in[11]};
    for (int i = 0; i < 7; i++) {
        sa.src[i] = srcs[i];
        if (i < 3) {
            sa.hi[i] = xhi + (size_t)i*XN;
            sa.lo[i] = xlo + (size_t)i*XN;
            sa.n[i]  = XN;
        } else {
            sa.hi[i] = whi + (size_t)(i-3)*WN;
            sa.lo[i] = wlo + (size_t)(i-3)*WN;
            sa.n[i]  = WN;
        }
    }
    split_kernel<<<dim3((XN/4 + 255)/256, 7), 256>>>(sa);
    ebuild_kernel<<<(EROWS*128 + 255)/256, 256>>>(Ek, Eq);

    dim3 qkvGrid(D_/BN, (B_*S_)/BM, 3);
    mma_gemm_kernel<0><<<qkvGrid, 256, 2*GSTAGE>>>(bq, bk, bv, nullptr);

    bias_mma_kernel<<<dim3(4, H_, B_), 256>>>();
    attn_kernel<<<dim3(S_/QT, H_, B_), 256, SMEM_ATTN>>>(mask, Ev);

    dim3 oGrid(D_/BN, (B_*S_)/BM, 1);
    mma_gemm_kernel<1><<<oGrid, 256, 2*GSTAGE>>>(bo, nullptr, nullptr, out);
}

// round 9
// speedup vs baseline: 1.0518x; 1.0518x over previous
#include <cuda_runtime.h>
#include <cuda_bf16.h>
#include <cstdint>
#include <cstddef>

#define B_    4
#define S_    512
#define D_    768
#define H_    12
#define HD_   64
#define NRELV 101
#define EROWS 112
#define XN    (B_*S_*D_)
#define WN    (D_*D_)

#define BM    128
#define BN    128
#define BK    32
#define LDSB  40           // bf16 stride (80B) -> ldmatrix conflict-free
#define GSTAGE 40960       // bytes per gemm pipeline stage

// ---------------- scratch ------------------------------------------------------
__device__ __nv_bfloat16 g_qkhi[(size_t)B_*H_*S_*128], g_qklo[(size_t)B_*H_*S_*128];
__device__ __nv_bfloat16 g_vhi[XN], g_vlo[XN];
__device__ __nv_bfloat16 g_xhi[3*XN], g_xlo[3*XN];
__device__ __nv_bfloat16 g_whi[4*WN], g_wlo[4*WN];
__device__ __nv_bfloat16 g_chi[XN], g_clo[XN];
__device__ __nv_bfloat16 g_ehi[EROWS*128], g_elo[EROWS*128];
__device__ float   g_bias[(size_t)B_*H_*S_*NRELV];
__device__ uint8_t g_rel8[(size_t)B_*S_*S_];
__device__ int     g_arc_is64;

// ---------------- helpers ------------------------------------------------------
__device__ __forceinline__ void split2(float a, float b, uint32_t& hi, uint32_t& lo)
{
    __nv_bfloat16 h0 = __float2bfloat16(a);
    __nv_bfloat16 h1 = __float2bfloat16(b);
    __nv_bfloat16 l0 = __float2bfloat16(a - __bfloat162float(h0));
    __nv_bfloat16 l1 = __float2bfloat16(b - __bfloat162float(h1));
    hi = (uint32_t)*(unsigned short*)&h0 | ((uint32_t)*(unsigned short*)&h1 << 16);
    lo = (uint32_t)*(unsigned short*)&l0 | ((uint32_t)*(unsigned short*)&l1 << 16);
}

__device__ __forceinline__ void ldsm_x4(uint32_t addr, uint32_t& r0, uint32_t& r1,
                                        uint32_t& r2, uint32_t& r3)
{
    asm volatile("ldmatrix.sync.aligned.m8n8.x4.shared.b16 {%0,%1,%2,%3}, [%4];"
                 : "=r"(r0), "=r"(r1), "=r"(r2), "=r"(r3) : "r"(addr));
}

__device__ __forceinline__ void ldsm_x2_trans(uint32_t addr, uint32_t& r0, uint32_t& r1)
{
    asm volatile("ldmatrix.sync.aligned.m8n8.x2.trans.shared.b16 {%0,%1}, [%2];"
                 : "=r"(r0), "=r"(r1) : "r"(addr));
}

__device__ __forceinline__ void mma16816(float* c, const uint32_t* a,
                                         uint32_t b0, uint32_t b1)
{
    asm volatile(
        "mma.sync.aligned.m16n8k16.row.col.f32.bf16.bf16.f32 "
        "{%0,%1,%2,%3}, {%4,%5,%6,%7}, {%8,%9}, {%0,%1,%2,%3};"
        : "+f"(c[0]), "+f"(c[1]), "+f"(c[2]), "+f"(c[3])
        : "r"(a[0]), "r"(a[1]), "r"(a[2]), "r"(a[3]), "r"(b0), "r"(b1));
}

__device__ __forceinline__ void cp16(uint32_t dst, const void* src)
{
    asm volatile("cp.async.ca.shared.global [%0], [%1], 16;" :: "r"(dst), "l"(src));
}

// ---------------- graph_arc dtype detection ------------------------------------
__global__ void detect_kernel(const int* __restrict__ arc32)
{
    __shared__ int cnt;
    if (threadIdx.x == 0) cnt = 0;
    __syncthreads();
    int local = 0;
    for (int i = threadIdx.x; i < 1024; i += blockDim.x)
        if (arc32[2*i + 1] != 0) local++;
    if (local) atomicAdd(&cnt, local);
    __syncthreads();
    if (threadIdx.x == 0) g_arc_is64 = (cnt == 0) ? 1 : 0;
}

// arc (int32 or int64) -> uint8 relation table
__global__ void __launch_bounds__(256)
rel8_kernel(const void* __restrict__ arc)
{
    const int is64 = g_arc_is64;
    const size_t i = ((size_t)blockIdx.x * 256 + threadIdx.x) * 4;
    if (i >= (size_t)B_*S_*S_) return;
    uchar4 r;
    if (is64) {
        const long long* a = (const long long*)arc + i;
        r = make_uchar4((uint8_t)a[0], (uint8_t)a[1], (uint8_t)a[2], (uint8_t)a[3]);
    } else {
        const int* a = (const int*)arc + i;
        r = make_uchar4((uint8_t)a[0], (uint8_t)a[1], (uint8_t)a[2], (uint8_t)a[3]);
    }
    *(uchar4*)&g_rel8[i] = r;
}

// ---------------- prepass: fp32 -> bf16 hi/lo split -----------------------------
struct SplitArgs {
    const float*   src[7];
    __nv_bfloat16* hi[7];
    __nv_bfloat16* lo[7];
    int            n[7];
};

__global__ void __launch_bounds__(256)
split_kernel(SplitArgs a)
{
    const int w = blockIdx.y;
    const int n = a.n[w];
    const int i = (blockIdx.x * 256 + threadIdx.x) * 4;
    if (i >= n) return;
    float4 v = *(const float4*)(a.src[w] + i);
    uint32_t h0, l0, h1, l1;
    split2(v.x, v.y, h0, l0);
    split2(v.z, v.w, h1, l1);
    *(uint2*)(a.hi[w] + i) = make_uint2(h0, h1);
    *(uint2*)(a.lo[w] + i) = make_uint2(l0, l1);
}

__global__ void __launch_bounds__(256)
ebuild_kernel(const float* __restrict__ Ek, const float* __restrict__ Eq)
{
    int idx = blockIdx.x * 256 + threadIdx.x;
    if (idx >= EROWS*128) return;
    int row = idx >> 7, col = idx & 127;
    float v = 0.f;
    if (row < NRELV) v = (col < 64) ? Ek[row*64 + col] : Eq[row*64 + col - 64];
    __nv_bfloat16 hv = __float2bfloat16(v);
    __nv_bfloat16 lv = __float2bfloat16(v - __bfloat162float(hv));
    g_ehi[idx] = hv;
    g_elo[idx] = lv;
}

// ---------------- tensor-core GEMM, cp.async 2-stage pipeline -------------------
template<int MODE>
__global__ void __launch_bounds__(256, 2)
mma_gemm_kernel(const float* __restrict__ bias0, const float* __restrict__ bias1,
                const float* __restrict__ bias2, float* __restrict__ out1)
{
    extern __shared__ char gsm[];
    const uint32_t smemBase = (uint32_t)__cvta_generic_to_shared(gsm);

    const int z = (MODE == 0) ? blockIdx.z : 0;
    const __nv_bfloat16 *Xhi, *Xlo, *Whi, *Wlo;
    const float* bias;
    if (MODE == 0) {
        Xhi = g_xhi + (size_t)z*XN;  Xlo = g_xlo + (size_t)z*XN;
        Whi = g_whi + (size_t)z*WN;  Wlo = g_wlo + (size_t)z*WN;
        bias = (z == 0) ? bias0 : (z == 1) ? bias1 : bias2;
    } else {
        Xhi = g_chi;  Xlo = g_clo;
        Whi = g_whi + (size_t)3*WN;  Wlo = g_wlo + (size_t)3*WN;
        bias = bias0;
    }

    const int tid  = threadIdx.x;
    const int lane = tid & 31;
    const int warp = tid >> 5;
    const int wm   = warp & 3;
    const int wn   = warp >> 2;
    const int m0   = blockIdx.y * BM;
    const int n0   = blockIdx.x * BN;

    float acc[2][8][4];
    #pragma unroll
    for (int mt = 0; mt < 2; mt++)
        #pragma unroll
        for (int nt = 0; nt < 8; nt++)
            #pragma unroll
            for (int j = 0; j < 4; j++) acc[mt][nt][j] = 0.f;

    const int mat = lane >> 3, mr = lane & 7;
    const uint32_t aOffHi = (uint32_t)((wm*32 + (mat & 1)*8 + mr)*80 + ((mat >> 1)*8)*2);
    const uint32_t bOffHi = 20480u + (uint32_t)((wn*64 + (mat >> 1)*8 + mr)*80 + ((mat & 1)*8)*2);

    const int ldrow = tid >> 1;
    const int ldq   = (tid & 1) * 2;
    const uint32_t xDst = (uint32_t)(ldrow*80 + ldq*16);
    const uint32_t wDst = 20480u + xDst;

    #pragma unroll
    for (int u = 0; u < 2; u++) {
        const size_t xo = (size_t)(m0 + ldrow)*D_ + (ldq + u)*8;
        const size_t wo = (size_t)(n0 + ldrow)*D_ + (ldq + u)*8;
        cp16(smemBase + xDst + u*16,          Xhi + xo);
        cp16(smemBase + 10240 + xDst + u*16,  Xlo + xo);
        cp16(smemBase + wDst + u*16,          Whi + wo);
        cp16(smemBase + 10240 + wDst + u*16,  Wlo + wo);
    }
    asm volatile("cp.async.commit_group;");

    const int NK = D_ / BK;
    for (int kt = 0; kt < NK; kt++) {
        asm volatile("cp.async.wait_group 0;");
        __syncthreads();

        if (kt + 1 < NK) {
            const uint32_t sb2 = smemBase + (uint32_t)(((kt + 1) & 1) * GSTAGE);
            const int k0 = (kt + 1) * BK;
            #pragma unroll
            for (int u = 0; u < 2; u++) {
                const size_t xo = (size_t)(m0 + ldrow)*D_ + k0 + (ldq + u)*8;
                const size_t wo = (size_t)(n0 + ldrow)*D_ + k0 + (ldq + u)*8;
                cp16(sb2 + xDst + u*16,          Xhi + xo);
                cp16(sb2 + 10240 + xDst + u*16,  Xlo + xo);
                cp16(sb2 + wDst + u*16,          Whi + wo);
                cp16(sb2 + 10240 + wDst + u*16,  Wlo + wo);
            }
        }
        asm volatile("cp.async.commit_group;");

        const uint32_t sb = smemBase + (uint32_t)((kt & 1) * GSTAGE);
        #pragma unroll
        for (int ks = 0; ks < 2; ks++) {
            const uint32_t ko = ks * 32;
            uint32_t ah[2][4], al[2][4];
            #pragma unroll
            for (int mt = 0; mt < 2; mt++) {
                const uint32_t mo = mt * 1280;
                ldsm_x4(sb + aOffHi + mo + ko,          ah[mt][0], ah[mt][1], ah[mt][2], ah[mt][3]);
                ldsm_x4(sb + aOffHi + 10240 + mo + ko,  al[mt][0], al[mt][1], al[mt][2], al[mt][3]);
            }
            #pragma unroll
            for (int pr = 0; pr < 4; pr++) {
                const uint32_t po = pr * 1280;
                uint32_t bh[4], bl[4];
                ldsm_x4(sb + bOffHi + po + ko,          bh[0], bh[1], bh[2], bh[3]);
                ldsm_x4(sb + bOffHi + 10240 + po + ko,  bl[0], bl[1], bl[2], bl[3]);
                #pragma unroll
                for (int h2 = 0; h2 < 2; h2++) {
                    const int nt = pr*2 + h2;
                    #pragma unroll
                    for (int mt = 0; mt < 2; mt++) {
                        mma16816(acc[mt][nt], ah[mt], bh[h2*2], bh[h2*2+1]);
                        mma16816(acc[mt][nt], ah[mt], bl[h2*2], bl[h2*2+1]);
                        mma16816(acc[mt][nt], al[mt], bh[h2*2], bh[h2*2+1]);
                    }
                }
            }
        }
    }

    const int gid = lane >> 2, tig = lane & 3;
    #pragma unroll
    for (int mt = 0; mt < 2; mt++) {
        const int rbase = m0 + wm*32 + mt*16 + gid;
        #pragma unroll
        for (int nt = 0; nt < 8; nt++) {
            const int col = n0 + wn*64 + nt*8 + tig*2;
            const float b0v = bias[col], b1v = bias[col+1];
            float v00 = acc[mt][nt][0] + b0v;
            float v01 = acc[mt][nt][1] + b1v;
            float v10 = acc[mt][nt][2] + b0v;
            float v11 = acc[mt][nt][3] + b1v;
            if (MODE == 0) {
                const int hh = col >> 6, e = col & 63;
                #pragma unroll
                for (int half = 0; half < 2; half++) {
                    const int r = rbase + half*8;
                    const int b = r >> 9, s = r & (S_-1);
                    const size_t rowb = (size_t)(b*H_ + hh)*S_ + s;
                    const float va = half ? v10 : v00;
                    const float vb = half ? v11 : v01;
                    uint32_t hi, lo; split2(va, vb, hi, lo);
                    if (z == 0) {
                        *(uint32_t*)&g_qkhi[rowb*128 + e] = hi;
                        *(uint32_t*)&g_qklo[rowb*128 + e] = lo;
                    } else if (z == 1) {
                        *(uint32_t*)&g_qkhi[rowb*128 + 64 + e] = hi;
                        *(uint32_t*)&g_qklo[rowb*128 + 64 + e] = lo;
                    } else {
                        *(uint32_t*)&g_vhi[rowb*64 + e] = hi;
                        *(uint32_t*)&g_vlo[rowb*64 + e] = lo;
                    }
                }
            } else {
                out1[(size_t)rbase*D_ + col]       = v00;
                out1[(size_t)rbase*D_ + col + 1]   = v01;
                out1[(size_t)(rbase+8)*D_ + col]   = v10;
                out1[(size_t)(rbase+8)*D_ + col+1] = v11;
            }
        }
    }
}

// ---------------- bias table via tensor cores -----------------------------------
__global__ void __launch_bounds__(256, 1)
bias_mma_kernel()
{
    __shared__ __nv_bfloat16 sAhi[128][LDSB], sAlo[128][LDSB];
    __shared__ __nv_bfloat16 sBhi[EROWS][LDSB], sBlo[EROWS][LDSB];

    const int rt = blockIdx.x;
    const int h  = blockIdx.y, b = blockIdx.z;
    const size_t bh = (size_t)b*H_ + h;
    const size_t abase = (bh*S_ + rt*128) * 128;

    const int tid  = threadIdx.x;
    const int lane = tid & 31;
    const int warp = tid >> 5;

    float acc[14][4];
    #pragma unroll
    for (int nt = 0; nt < 14; nt++)
        #pragma unroll
        for (int j = 0; j < 4; j++) acc[nt][j] = 0.f;

    const int mat = lane >> 3, mr = lane & 7;
    const int a_row = (mat & 1) * 8 + mr;
    const int a_k   = (mat >> 1) * 8;
    const uint32_t aHi = (uint32_t)__cvta_generic_to_shared(&sAhi[warp*16 + a_row][a_k]);
    const uint32_t aLo = (uint32_t)__cvta_generic_to_shared(&sAlo[warp*16 + a_row][a_k]);
    const int b_row = (mat >> 1) * 8 + mr;
    const int b_k   = (mat & 1) * 8;
    const uint32_t bHi = (uint32_t)__cvta_generic_to_shared(&sBhi[b_row][b_k]);
    const uint32_t bLo = (uint32_t)__cvta_generic_to_shared(&sBlo[b_row][b_k]);

    for (int k0 = 0; k0 < 128; k0 += BK) {
        {
            const int arow = tid >> 1;
            const int acol = (tid & 1) * 16;
            const size_t src = abase + (size_t)arow*128 + k0 + acol;
            uint4 h0 = *(const uint4*)(g_qkhi + src);
            uint4 h1 = *(const uint4*)(g_qkhi + src + 8);
            uint4 l0 = *(const uint4*)(g_qklo + src);
            uint4 l1 = *(const uint4*)(g_qklo + src + 8);
            __syncthreads();
            *(uint4*)&sAhi[arow][acol]     = h0;
            *(uint4*)&sAhi[arow][acol + 8] = h1;
            *(uint4*)&sAlo[arow][acol]     = l0;
            *(uint4*)&sAlo[arow][acol + 8] = l1;
        }
        if (tid < EROWS*2) {
            const int brow = tid >> 1;
            const int bcol = (tid & 1) * 16;
            const size_t src = (size_t)brow*128 + k0 + bcol;
            *(uint4*)&sBhi[brow][bcol]     = *(const uint4*)(g_ehi + src);
            *(uint4*)&sBhi[brow][bcol + 8] = *(const uint4*)(g_ehi + src + 8);
            *(uint4*)&sBlo[brow][bcol]     = *(const uint4*)(g_elo + src);
            *(uint4*)&sBlo[brow][bcol + 8] = *(const uint4*)(g_elo + src + 8);
        }
        __syncthreads();

        #pragma unroll
        for (int ks = 0; ks < 2; ks++) {
            const uint32_t ko = ks * 32;
            uint32_t ah[4], al[4];
            ldsm_x4(aHi + ko, ah[0], ah[1], ah[2], ah[3]);
            ldsm_x4(aLo + ko, al[0], al[1], al[2], al[3]);
            #pragma unroll
            for (int pr = 0; pr < 7; pr++) {
                const uint32_t po = pr * (16 * LDSB * 2);
                uint32_t bhf[4], blf[4];
                ldsm_x4(bHi + po + ko, bhf[0], bhf[1], bhf[2], bhf[3]);
                ldsm_x4(bLo + po + ko, blf[0], blf[1], blf[2], blf[3]);
                #pragma unroll
                for (int h2 = 0; h2 < 2; h2++) {
                    const int nt = pr*2 + h2;
                    mma16816(acc[nt], ah, bhf[h2*2], bhf[h2*2+1]);
                    mma16816(acc[nt], ah, blf[h2*2], blf[h2*2+1]);
                    mma16816(acc[nt], al, bhf[h2*2], bhf[h2*2+1]);
                }
            }
        }
        __syncthreads();
    }

    const int gid = lane >> 2, tig = lane & 3;
    const int row0 = rt*128 + warp*16 + gid;
    #pragma unroll
    for (int nt = 0; nt < 14; nt++) {
        const int col = nt*8 + tig*2;
        #pragma unroll
        for (int half = 0; half < 2; half++) {
            const int row = row0 + half*8;
            const size_t o = (bh*S_ + row)*NRELV;
            const float v0 = acc[nt][half*2];
            const float v1 = acc[nt][half*2+1];
            if (col < NRELV)     g_bias[o + col]     = v0;
            if (col + 1 < NRELV) g_bias[o + col + 1] = v1;
        }
    }
}

// ---------------- fused attention: QT=32 rows, 512 threads ----------------------
#define QT    32
#define SSTR  520
#define OFF_SS    0                       // 32*520*4 = 66560
#define OFF_KHI   66560                   // 128*72*2 = 18432
#define OFF_KLO   84992                   // -> 103424
#define OFF_EV    66560                   // Ev fp32 101*64 (reuses K region)
#define OFF_SB    103424                  // 32*101*4 = 12928
#define OFF_SW    116352                  // 12928
#define OFF_SZ    129280                  // 128
#define OFF_MASK  129408                  // 2048
#define SMEM_ATTN 131456

__global__ void __launch_bounds__(512, 1)
attn_kernel(const int* __restrict__ mask, const float* __restrict__ Ev)
{
    extern __shared__ char smraw[];
    float* sS    = (float*)(smraw + OFF_SS);
    __nv_bfloat16* sKhi = (__nv_bfloat16*)(smraw + OFF_KHI);
    __nv_bfloat16* sKlo = (__nv_bfloat16*)(smraw + OFF_KLO);
    float* sEv   = (float*)(smraw + OFF_EV);
    float* sB    = (float*)(smraw + OFF_SB);
    float* sW    = (float*)(smraw + OFF_SW);
    float* sZ    = (float*)(smraw + OFF_SZ);
    int*   sMask = (int*)  (smraw + OFF_MASK);

    const int qt = blockIdx.x, h = blockIdx.y, b = blockIdx.z;
    const int i0 = qt * QT;
    const int tid  = threadIdx.x;
    const int lane = tid & 31;
    const int warp = tid >> 5;        // 0..15
    const int mt   = warp >> 3;       // m-tile 0/1
    const int wj   = warp & 7;        // j-slice
    const size_t bh    = (size_t)b*H_ + h;
    const size_t qrow0 = bh*S_ + i0;
    const size_t krow0 = bh*S_;
    const size_t vbase = bh*S_*HD_;

    for (int i = tid; i < QT*NRELV; i += 512) {
        sB[i] = g_bias[qrow0*NRELV + i];
        sW[i] = 0.f;
    }
    for (int i = tid; i < S_; i += 512) sMask[i] = mask[b*S_ + i];
    __syncthreads();

    // ---- Q A-fragments for this warp's m-tile ----
    uint32_t qah[4][4], qal[4][4];
    {
        const int qr = lane >> 2;
        const int qc = (lane & 3) * 2;
        const size_t qm = qrow0 + mt*16;
        #pragma unroll
        for (int kk = 0; kk < 4; kk++) {
            const size_t r0o = (qm + qr)*128     + kk*16 + qc;
            const size_t r1o = (qm + qr + 8)*128 + kk*16 + qc;
            qah[kk][0] = *(const uint32_t*)&g_qkhi[r0o];
            qah[kk][1] = *(const uint32_t*)&g_qkhi[r1o];
            qah[kk][2] = *(const uint32_t*)&g_qkhi[r0o + 8];
            qah[kk][3] = *(const uint32_t*)&g_qkhi[r1o + 8];
            qal[kk][0] = *(const uint32_t*)&g_qklo[r0o];
            qal[kk][1] = *(const uint32_t*)&g_qklo[r1o];
            qal[kk][2] = *(const uint32_t*)&g_qklo[r0o + 8];
            qal[kk][3] = *(const uint32_t*)&g_qklo[r1o + 8];
        }
    }

    const int copyrow = tid >> 2;           // 0..127
    const int cq      = (tid & 3) * 16;     // element offset

    // ---- pass 1: S = Q K^T via mma ----
    for (int jt = 0; jt < 4; jt++) {
        const int j0 = jt * 128;
        {
            const size_t src = (krow0 + j0 + copyrow)*128 + 64 + cq;
            #pragma unroll
            for (int u = 0; u < 2; u++) {
                *(uint4*)&sKhi[copyrow*72 + cq + u*8] = *(const uint4*)(g_qkhi + src + u*8);
                *(uint4*)&sKlo[copyrow*72 + cq + u*8] = *(const uint4*)(g_qklo + src + u*8);
            }
        }
        __syncthreads();

        float c[2][4] = {{0,0,0,0},{0,0,0,0}};
        const int nw = wj * 16;
        #pragma unroll
        for (int kk = 0; kk < 4; kk++) {
            #pragma unroll
            for (int nt = 0; nt < 2; nt++) {
                const int j = nw + nt*8 + (lane >> 2);
                const int d = kk*16 + (lane & 3)*2;
                uint32_t bh0 = *(uint32_t*)&sKhi[j*72 + d];
                uint32_t bh1 = *(uint32_t*)&sKhi[j*72 + d + 8];
                uint32_t bl0 = *(uint32_t*)&sKlo[j*72 + d];
                uint32_t bl1 = *(uint32_t*)&sKlo[j*72 + d + 8];
                mma16816(c[nt], qah[kk], bh0, bh1);
                mma16816(c[nt], qah[kk], bl0, bl1);
                mma16816(c[nt], qal[kk], bh0, bh1);
            }
        }
        #pragma unroll
        for (int nt = 0; nt < 2; nt++) {
            const int col = j0 + nw + nt*8 + 2*(lane & 3);
            const int r   = mt*16 + (lane >> 2);
            *(float2*)&sS[r*SSTR + col]     = make_float2(c[nt][0], c[nt][1]);
            *(float2*)&sS[(r+8)*SSTR + col] = make_float2(c[nt][2], c[nt][3]);
        }
        __syncthreads();
    }

    // ---- relation bias + scale + mask (rel from u8 table, uchar4) ----
    const size_t arcbase = ((size_t)b*S_ + i0)*S_;
    for (int idx4 = tid; idx4 < QT*S_/4; idx4 += 512) {
        const int idx = idx4 * 4;
        const int i = idx >> 9, j = idx & (S_-1);
        uchar4 r4 = *(const uchar4*)&g_rel8[arcbase + (size_t)i*S_ + j];
        const float* brow = &sB[i*NRELV];
        float4 s4 = *(float4*)&sS[i*SSTR + j];
        s4.x = (s4.x + brow[r4.x]) * 0.125f; if (sMask[j]     == 0) s4.x = -1e30f;
        s4.y = (s4.y + brow[r4.y]) * 0.125f; if (sMask[j + 1] == 0) s4.y = -1e30f;
        s4.z = (s4.z + brow[r4.z]) * 0.125f; if (sMask[j + 2] == 0) s4.z = -1e30f;
        s4.w = (s4.w + brow[r4.w]) * 0.125f; if (sMask[j + 3] == 0) s4.w = -1e30f;
        *(float4*)&sS[i*SSTR + j] = s4;
    }
    __syncthreads();

    // ---- softmax (unnormalized exp; Z per row) ----
    #pragma unroll
    for (int rr = 0; rr < 2; rr++) {
        int row = warp*2 + rr;
        float m = -3.4e38f;
        for (int j = lane; j < S_; j += 32) m = fmaxf(m, sS[row*SSTR + j]);
        #pragma unroll
        for (int o = 16; o; o >>= 1) m = fmaxf(m, __shfl_xor_sync(0xffffffffu, m, o));
        float z = 0.f;
        for (int j = lane; j < S_; j += 32) {
            float p = __expf(sS[row*SSTR + j] - m);
            sS[row*SSTR + j] = p;
            z += p;
        }
        #pragma unroll
        for (int o = 16; o; o >>= 1) z += __shfl_xor_sync(0xffffffffu, z, o);
        if (lane == 0) sZ[row] = z;
    }
    __syncthreads();

    // ---- relation binning (rel from u8 table) ----
    for (int idx4 = tid; idx4 < QT*S_/4; idx4 += 512) {
        const int idx = idx4 * 4;
        const int i = idx >> 9, j = idx & (S_-1);
        uchar4 r4 = *(const uchar4*)&g_rel8[arcbase + (size_t)i*S_ + j];
        float4 p4 = *(float4*)&sS[i*SSTR + j];
        float* wrow = &sW[i*NRELV];
        atomicAdd(&wrow[r4.x], p4.x);
        atomicAdd(&wrow[r4.y], p4.y);
        atomicAdd(&wrow[r4.z], p4.z);
        atomicAdd(&wrow[r4.w], p4.w);
    }
    __syncthreads();

    // ---- pass 2: ctx = P V via mma ----
    float c2[8][4];
    #pragma unroll
    for (int nt = 0; nt < 8; nt++)
        #pragma unroll
        for (int j = 0; j < 4; j++) c2[nt][j] = 0.f;

    const uint32_t vhiBase = (uint32_t)__cvta_generic_to_shared(sKhi);
    const uint32_t vloBase = (uint32_t)__cvta_generic_to_shared(sKlo);
    for (int jt = 0; jt < 4; jt++) {
        {
            const size_t src = vbase + (size_t)(jt*128 + copyrow)*HD_ + cq;
            #pragma unroll
            for (int u = 0; u < 2; u++) {
                *(uint4*)&sKhi[copyrow*72 + cq + u*8] = *(const uint4*)(g_vhi + src + u*8);
                *(uint4*)&sKlo[copyrow*72 + cq + u*8] = *(const uint4*)(g_vlo + src + u*8);
            }
        }
        __syncthreads();

        const int jb = jt*128 + wj*16;
        uint32_t pah[4], pal[4];
        {
            const int pr = mt*16 + (lane >> 2);
            const int pc = (lane & 3) * 2;
            float2 x0 = *(float2*)&sS[pr*SSTR     + jb + pc];
            float2 x1 = *(float2*)&sS[(pr+8)*SSTR + jb + pc];
            float2 x2 = *(float2*)&sS[pr*SSTR     + jb + pc + 8];
            float2 x3 = *(float2*)&sS[(pr+8)*SSTR + jb + pc + 8];
            split2(x0.x, x0.y, pah[0], pal[0]);
            split2(x1.x, x1.y, pah[1], pal[1]);
            split2(x2.x, x2.y, pah[2], pal[2]);
            split2(x3.x, x3.y, pah[3], pal[3]);
        }
        const uint32_t rowoff = (uint32_t)(wj*16 + (lane & 15)) * 144;
        #pragma unroll
        for (int nt = 0; nt < 8; nt++) {
            uint32_t bh0, bh1, bl0, bl1;
            ldsm_x2_trans(vhiBase + rowoff + nt*16, bh0, bh1);
            ldsm_x2_trans(vloBase + rowoff + nt*16, bl0, bl1);
            mma16816(c2[nt], pah, bh0, bh1);
            mma16816(c2[nt], pah, bl0, bl1);
            mma16816(c2[nt], pal, bh0, bh1);
        }
        __syncthreads();
    }

    // ---- PV partials to smem (reuse sS) + load Ev ----
    {
        float* red = sS;
        const int r = lane >> 2;
        #pragma unroll
        for (int nt = 0; nt < 8; nt++) {
            const int col = nt*8 + 2*(lane & 3);
            red[warp*1024 + r*64 + col]       = c2[nt][0];
            red[warp*1024 + r*64 + col + 1]   = c2[nt][1];
            red[warp*1024 + (r+8)*64 + col]   = c2[nt][2];
            red[warp*1024 + (r+8)*64 + col+1] = c2[nt][3];
        }
    }
    for (int i = tid; i < NRELV*HD_; i += 512) sEv[i] = Ev[i];
    __syncthreads();

    // ---- final: reduce 8 partials, + wrel@Ev, /Z, store ctx hi/lo ----
    {
        const int row = tid >> 4;            // 0..31
        const int e0  = (tid & 15) * 4;
        const int rmt = row >> 4, rl = row & 15;
        float4 acc = make_float4(0,0,0,0);
        #pragma unroll
        for (int w = 0; w < 8; w++) {
            float4 p = *(float4*)&sS[(rmt*8 + w)*1024 + rl*64 + e0];
            acc.x += p.x; acc.y += p.y; acc.z += p.z; acc.w += p.w;
        }
        const float* wrow = &sW[row*NRELV];
        for (int rel = 0; rel < NRELV; rel++) {
            float wv = wrow[rel];
            float4 ev = *(float4*)&sEv[rel*64 + e0];
            acc.x += wv*ev.x; acc.y += wv*ev.y; acc.z += wv*ev.z; acc.w += wv*ev.w;
        }
        const float rz = 1.f / sZ[row];
        acc.x *= rz; acc.y *= rz; acc.z *= rz; acc.w *= rz;

        uint32_t h0, l0, h1, l1;
        split2(acc.x, acc.y, h0, l0);
        split2(acc.z, acc.w, h1, l1);
        const size_t o = ((size_t)(b*S_ + i0 + row))*D_ + h*HD_ + e0;
        *(uint2*)&g_chi[o] = make_uint2(h0, h1);
        *(uint2*)&g_clo[o] = make_uint2(l0, l1);
    }
}

// ---------------- launch --------------------------------------------------------
extern "C" void kernel_launch(void* const* d_in, const int* in_sizes, int n_in,
                              void* d_out, int out_size)
{
    (void)in_sizes; (void)n_in; (void)out_size;
    const float* query = (const float*)d_in[0];
    const float* key_  = (const float*)d_in[1];
    const float* value = (const float*)d_in[2];
    const int*   mask  = (const int*)d_in[3];
    const void*  arc   = d_in[4];
    const float* bq = (const float*)d_in[6];
    const float* bk = (const float*)d_in[8];
    const float* bv = (const float*)d_in[10];
    const float* bo = (const float*)d_in[12];
    const float* Ek = (const float*)d_in[13];
    const float* Eq = (const float*)d_in[14];
    const float* Ev = (const float*)d_in[15];
    float* out = (float*)d_out;

    cudaFuncSetAttribute(attn_kernel, cudaFuncAttributeMaxDynamicSharedMemorySize, SMEM_ATTN);
    cudaFuncSetAttribute(mma_gemm_kernel<0>, cudaFuncAttributeMaxDynamicSharedMemorySize, 2*GSTAGE);
    cudaFuncSetAttribute(mma_gemm_kernel<1>, cudaFuncAttributeMaxDynamicSharedMemorySize, 2*GSTAGE);

    __nv_bfloat16 *xhi, *xlo, *whi, *wlo;
    cudaGetSymbolAddress((void**)&xhi, g_xhi);
    cudaGetSymbolAddress((void**)&xlo, g_xlo);
    cudaGetSymbolAddress((void**)&whi, g_whi);
    cudaGetSymbolAddress((void**)&wlo, g_wlo);

    detect_kernel<<<1, 256>>>((const int*)arc);
    rel8_kernel<<<((B_*S_*S_/4) + 255)/256, 256>>>(arc);

    SplitArgs sa;
    const float* srcs[7] = {query, key_, value,
                            (const float*)d_in[5], (const float*)d_in[7],
                            (const float*)d_in[9], (const float*)d_in[11]};
    for (int i = 0; i < 7; i++) {
        sa.src[i] = srcs[i];
        if (i < 3) {
            sa.hi[i] = xhi + (size_t)i*XN;
            sa.lo[i] = xlo + (size_t)i*XN;
            sa.n[i]  = XN;
        } else {
            sa.hi[i] = whi + (size_t)(i-3)*WN;
            sa.lo[i] = wlo + (size_t)(i-3)*WN;
            sa.n[i]  = WN;
        }
    }
    split_kernel<<<dim3((XN/4 + 255)/256, 7), 256>>>(sa);
    ebuild_kernel<<<(EROWS*128 + 255)/256, 256>>>(Ek, Eq);

    dim3 qkvGrid(D_/BN, (B_*S_)/BM, 3);
    mma_gemm_kernel<0><<<qkvGrid, 256, 2*GSTAGE>>>(bq, bk, bv, nullptr);

    bias_mma_kernel<<<dim3(4, H_, B_), 256>>>();
    attn_kernel<<<dim3(S_/QT, H_, B_), 512, SMEM_ATTN>>>(mask, Ev);

    dim3 oGrid(D_/BN, (B_*S_)/BM, 1);
    mma_gemm_kernel<1><<<oGrid, 256, 2*GSTAGE>>>(bo, nullptr, nullptr, out);
}

// round 10
// speedup vs baseline: 1.1036x; 1.0492x over previous
#include <cuda_runtime.h>
#include <cuda_bf16.h>
#include <cstdint>
#include <cstddef>

#define B_    4
#define S_    512
#define D_    768
#define H_    12
#define HD_   64
#define NRELV 101
#define EROWS 112
#define XN    (B_*S_*D_)
#define WN    (D_*D_)

#define BM    128
#define BN    128
#define BK    32
#define LDSB  40           // bf16 stride (80B) -> ldmatrix conflict-free
#define GSTAGE 40960       // bytes per gemm pipeline stage

// ---------------- scratch ------------------------------------------------------
__device__ __nv_bfloat16 g_qkhi[(size_t)B_*H_*S_*128], g_qklo[(size_t)B_*H_*S_*128];
__device__ __nv_bfloat16 g_vhi[XN], g_vlo[XN];
__device__ __nv_bfloat16 g_xhi[3*XN], g_xlo[3*XN];
__device__ __nv_bfloat16 g_whi[4*WN], g_wlo[4*WN];
__device__ __nv_bfloat16 g_chi[XN], g_clo[XN];
__device__ __nv_bfloat16 g_ehi[EROWS*128], g_elo[EROWS*128];
__device__ float   g_bias[(size_t)B_*H_*S_*NRELV];
__device__ uint8_t g_rel8[(size_t)B_*S_*S_];
__device__ int     g_arc_is64;

// ---------------- helpers ------------------------------------------------------
__device__ __forceinline__ void split2(float a, float b, uint32_t& hi, uint32_t& lo)
{
    __nv_bfloat16 h0 = __float2bfloat16(a);
    __nv_bfloat16 h1 = __float2bfloat16(b);
    __nv_bfloat16 l0 = __float2bfloat16(a - __bfloat162float(h0));
    __nv_bfloat16 l1 = __float2bfloat16(b - __bfloat162float(h1));
    hi = (uint32_t)*(unsigned short*)&h0 | ((uint32_t)*(unsigned short*)&h1 << 16);
    lo = (uint32_t)*(unsigned short*)&l0 | ((uint32_t)*(unsigned short*)&l1 << 16);
}

__device__ __forceinline__ void ldsm_x4(uint32_t addr, uint32_t& r0, uint32_t& r1,
                                        uint32_t& r2, uint32_t& r3)
{
    asm volatile("ldmatrix.sync.aligned.m8n8.x4.shared.b16 {%0,%1,%2,%3}, [%4];"
                 : "=r"(r0), "=r"(r1), "=r"(r2), "=r"(r3) : "r"(addr));
}

__device__ __forceinline__ void ldsm_x2_trans(uint32_t addr, uint32_t& r0, uint32_t& r1)
{
    asm volatile("ldmatrix.sync.aligned.m8n8.x2.trans.shared.b16 {%0,%1}, [%2];"
                 : "=r"(r0), "=r"(r1) : "r"(addr));
}

__device__ __forceinline__ void mma16816(float* c, const uint32_t* a,
                                         uint32_t b0, uint32_t b1)
{
    asm volatile(
        "mma.sync.aligned.m16n8k16.row.col.f32.bf16.bf16.f32 "
        "{%0,%1,%2,%3}, {%4,%5,%6,%7}, {%8,%9}, {%0,%1,%2,%3};"
        : "+f"(c[0]), "+f"(c[1]), "+f"(c[2]), "+f"(c[3])
        : "r"(a[0]), "r"(a[1]), "r"(a[2]), "r"(a[3]), "r"(b0), "r"(b1));
}

__device__ __forceinline__ void cp16(uint32_t dst, const void* src)
{
    asm volatile("cp.async.ca.shared.global [%0], [%1], 16;" :: "r"(dst), "l"(src));
}

// ---------------- graph_arc dtype detection ------------------------------------
__global__ void detect_kernel(const int* __restrict__ arc32)
{
    __shared__ int cnt;
    if (threadIdx.x == 0) cnt = 0;
    __syncthreads();
    int local = 0;
    for (int i = threadIdx.x; i < 1024; i += blockDim.x)
        if (arc32[2*i + 1] != 0) local++;
    if (local) atomicAdd(&cnt, local);
    __syncthreads();
    if (threadIdx.x == 0) g_arc_is64 = (cnt == 0) ? 1 : 0;
}

// arc (int32 or int64) -> uint8 relation table
__global__ void __launch_bounds__(256)
rel8_kernel(const void* __restrict__ arc)
{
    const int is64 = g_arc_is64;
    const size_t i = ((size_t)blockIdx.x * 256 + threadIdx.x) * 4;
    if (i >= (size_t)B_*S_*S_) return;
    uchar4 r;
    if (is64) {
        const long long* a = (const long long*)arc + i;
        r = make_uchar4((uint8_t)a[0], (uint8_t)a[1], (uint8_t)a[2], (uint8_t)a[3]);
    } else {
        const int* a = (const int*)arc + i;
        r = make_uchar4((uint8_t)a[0], (uint8_t)a[1], (uint8_t)a[2], (uint8_t)a[3]);
    }
    *(uchar4*)&g_rel8[i] = r;
}

// ---------------- prepass: fp32 -> bf16 hi/lo split -----------------------------
struct SplitArgs {
    const float*   src[7];
    __nv_bfloat16* hi[7];
    __nv_bfloat16* lo[7];
    int            n[7];
};

__global__ void __launch_bounds__(256)
split_kernel(SplitArgs a)
{
    const int w = blockIdx.y;
    const int n = a.n[w];
    const int i = (blockIdx.x * 256 + threadIdx.x) * 4;
    if (i >= n) return;
    float4 v = *(const float4*)(a.src[w] + i);
    uint32_t h0, l0, h1, l1;
    split2(v.x, v.y, h0, l0);
    split2(v.z, v.w, h1, l1);
    *(uint2*)(a.hi[w] + i) = make_uint2(h0, h1);
    *(uint2*)(a.lo[w] + i) = make_uint2(l0, l1);
}

__global__ void __launch_bounds__(256)
ebuild_kernel(const float* __restrict__ Ek, const float* __restrict__ Eq)
{
    int idx = blockIdx.x * 256 + threadIdx.x;
    if (idx >= EROWS*128) return;
    int row = idx >> 7, col = idx & 127;
    float v = 0.f;
    if (row < NRELV) v = (col < 64) ? Ek[row*64 + col] : Eq[row*64 + col - 64];
    __nv_bfloat16 hv = __float2bfloat16(v);
    __nv_bfloat16 lv = __float2bfloat16(v - __bfloat162float(hv));
    g_ehi[idx] = hv;
    g_elo[idx] = lv;
}

// ---------------- tensor-core GEMM, cp.async 2-stage pipeline -------------------
template<int MODE>
__global__ void __launch_bounds__(256, 2)
mma_gemm_kernel(const float* __restrict__ bias0, const float* __restrict__ bias1,
                const float* __restrict__ bias2, float* __restrict__ out1)
{
    extern __shared__ char gsm[];
    const uint32_t smemBase = (uint32_t)__cvta_generic_to_shared(gsm);

    const int z = (MODE == 0) ? blockIdx.z : 0;
    const __nv_bfloat16 *Xhi, *Xlo, *Whi, *Wlo;
    const float* bias;
    if (MODE == 0) {
        Xhi = g_xhi + (size_t)z*XN;  Xlo = g_xlo + (size_t)z*XN;
        Whi = g_whi + (size_t)z*WN;  Wlo = g_wlo + (size_t)z*WN;
        bias = (z == 0) ? bias0 : (z == 1) ? bias1 : bias2;
    } else {
        Xhi = g_chi;  Xlo = g_clo;
        Whi = g_whi + (size_t)3*WN;  Wlo = g_wlo + (size_t)3*WN;
        bias = bias0;
    }

    const int tid  = threadIdx.x;
    const int lane = tid & 31;
    const int warp = tid >> 5;
    const int wm   = warp & 3;
    const int wn   = warp >> 2;
    const int m0   = blockIdx.y * BM;
    const int n0   = blockIdx.x * BN;

    float acc[2][8][4];
    #pragma unroll
    for (int mt = 0; mt < 2; mt++)
        #pragma unroll
        for (int nt = 0; nt < 8; nt++)
            #pragma unroll
            for (int j = 0; j < 4; j++) acc[mt][nt][j] = 0.f;

    const int mat = lane >> 3, mr = lane & 7;
    const uint32_t aOffHi = (uint32_t)((wm*32 + (mat & 1)*8 + mr)*80 + ((mat >> 1)*8)*2);
    const uint32_t bOffHi = 20480u + (uint32_t)((wn*64 + (mat >> 1)*8 + mr)*80 + ((mat & 1)*8)*2);

    const int ldrow = tid >> 1;
    const int ldq   = (tid & 1) * 2;
    const uint32_t xDst = (uint32_t)(ldrow*80 + ldq*16);
    const uint32_t wDst = 20480u + xDst;

    #pragma unroll
    for (int u = 0; u < 2; u++) {
        const size_t xo = (size_t)(m0 + ldrow)*D_ + (ldq + u)*8;
        const size_t wo = (size_t)(n0 + ldrow)*D_ + (ldq + u)*8;
        cp16(smemBase + xDst + u*16,          Xhi + xo);
        cp16(smemBase + 10240 + xDst + u*16,  Xlo + xo);
        cp16(smemBase + wDst + u*16,          Whi + wo);
        cp16(smemBase + 10240 + wDst + u*16,  Wlo + wo);
    }
    asm volatile("cp.async.commit_group;");

    const int NK = D_ / BK;
    for (int kt = 0; kt < NK; kt++) {
        asm volatile("cp.async.wait_group 0;");
        __syncthreads();

        if (kt + 1 < NK) {
            const uint32_t sb2 = smemBase + (uint32_t)(((kt + 1) & 1) * GSTAGE);
            const int k0 = (kt + 1) * BK;
            #pragma unroll
            for (int u = 0; u < 2; u++) {
                const size_t xo = (size_t)(m0 + ldrow)*D_ + k0 + (ldq + u)*8;
                const size_t wo = (size_t)(n0 + ldrow)*D_ + k0 + (ldq + u)*8;
                cp16(sb2 + xDst + u*16,          Xhi + xo);
                cp16(sb2 + 10240 + xDst + u*16,  Xlo + xo);
                cp16(sb2 + wDst + u*16,          Whi + wo);
                cp16(sb2 + 10240 + wDst + u*16,  Wlo + wo);
            }
        }
        asm volatile("cp.async.commit_group;");

        const uint32_t sb = smemBase + (uint32_t)((kt & 1) * GSTAGE);
        #pragma unroll
        for (int ks = 0; ks < 2; ks++) {
            const uint32_t ko = ks * 32;
            uint32_t ah[2][4], al[2][4];
            #pragma unroll
            for (int mt = 0; mt < 2; mt++) {
                const uint32_t mo = mt * 1280;
                ldsm_x4(sb + aOffHi + mo + ko,          ah[mt][0], ah[mt][1], ah[mt][2], ah[mt][3]);
                ldsm_x4(sb + aOffHi + 10240 + mo + ko,  al[mt][0], al[mt][1], al[mt][2], al[mt][3]);
            }
            #pragma unroll
            for (int pr = 0; pr < 4; pr++) {
                const uint32_t po = pr * 1280;
                uint32_t bh[4], bl[4];
                ldsm_x4(sb + bOffHi + po + ko,          bh[0], bh[1], bh[2], bh[3]);
                ldsm_x4(sb + bOffHi + 10240 + po + ko,  bl[0], bl[1], bl[2], bl[3]);
                #pragma unroll
                for (int h2 = 0; h2 < 2; h2++) {
                    const int nt = pr*2 + h2;
                    #pragma unroll
                    for (int mt = 0; mt < 2; mt++) {
                        mma16816(acc[mt][nt], ah[mt], bh[h2*2], bh[h2*2+1]);
                        mma16816(acc[mt][nt], ah[mt], bl[h2*2], bl[h2*2+1]);
                        mma16816(acc[mt][nt], al[mt], bh[h2*2], bh[h2*2+1]);
                    }
                }
            }
        }
    }

    const int gid = lane >> 2, tig = lane & 3;
    #pragma unroll
    for (int mt = 0; mt < 2; mt++) {
        const int rbase = m0 + wm*32 + mt*16 + gid;
        #pragma unroll
        for (int nt = 0; nt < 8; nt++) {
            const int col = n0 + wn*64 + nt*8 + tig*2;
            const float b0v = bias[col], b1v = bias[col+1];
            float v00 = acc[mt][nt][0] + b0v;
            float v01 = acc[mt][nt][1] + b1v;
            float v10 = acc[mt][nt][2] + b0v;
            float v11 = acc[mt][nt][3] + b1v;
            if (MODE == 0) {
                const int hh = col >> 6, e = col & 63;
                #pragma unroll
                for (int half = 0; half < 2; half++) {
                    const int r = rbase + half*8;
                    const int b = r >> 9, s = r & (S_-1);
                    const size_t rowb = (size_t)(b*H_ + hh)*S_ + s;
                    const float va = half ? v10 : v00;
                    const float vb = half ? v11 : v01;
                    uint32_t hi, lo; split2(va, vb, hi, lo);
                    if (z == 0) {
                        *(uint32_t*)&g_qkhi[rowb*128 + e] = hi;
                        *(uint32_t*)&g_qklo[rowb*128 + e] = lo;
                    } else if (z == 1) {
                        *(uint32_t*)&g_qkhi[rowb*128 + 64 + e] = hi;
                        *(uint32_t*)&g_qklo[rowb*128 + 64 + e] = lo;
                    } else {
                        *(uint32_t*)&g_vhi[rowb*64 + e] = hi;
                        *(uint32_t*)&g_vlo[rowb*64 + e] = lo;
                    }
                }
            } else {
                out1[(size_t)rbase*D_ + col]       = v00;
                out1[(size_t)rbase*D_ + col + 1]   = v01;
                out1[(size_t)(rbase+8)*D_ + col]   = v10;
                out1[(size_t)(rbase+8)*D_ + col+1] = v11;
            }
        }
    }
}

// ---------------- bias table via tensor cores -----------------------------------
__global__ void __launch_bounds__(256, 1)
bias_mma_kernel()
{
    __shared__ __nv_bfloat16 sAhi[128][LDSB], sAlo[128][LDSB];
    __shared__ __nv_bfloat16 sBhi[EROWS][LDSB], sBlo[EROWS][LDSB];

    const int rt = blockIdx.x;
    const int h  = blockIdx.y, b = blockIdx.z;
    const size_t bh = (size_t)b*H_ + h;
    const size_t abase = (bh*S_ + rt*128) * 128;

    const int tid  = threadIdx.x;
    const int lane = tid & 31;
    const int warp = tid >> 5;

    float acc[14][4];
    #pragma unroll
    for (int nt = 0; nt < 14; nt++)
        #pragma unroll
        for (int j = 0; j < 4; j++) acc[nt][j] = 0.f;

    const int mat = lane >> 3, mr = lane & 7;
    const int a_row = (mat & 1) * 8 + mr;
    const int a_k   = (mat >> 1) * 8;
    const uint32_t aHi = (uint32_t)__cvta_generic_to_shared(&sAhi[warp*16 + a_row][a_k]);
    const uint32_t aLo = (uint32_t)__cvta_generic_to_shared(&sAlo[warp*16 + a_row][a_k]);
    const int b_row = (mat >> 1) * 8 + mr;
    const int b_k   = (mat & 1) * 8;
    const uint32_t bHi = (uint32_t)__cvta_generic_to_shared(&sBhi[b_row][b_k]);
    const uint32_t bLo = (uint32_t)__cvta_generic_to_shared(&sBlo[b_row][b_k]);

    for (int k0 = 0; k0 < 128; k0 += BK) {
        {
            const int arow = tid >> 1;
            const int acol = (tid & 1) * 16;
            const size_t src = abase + (size_t)arow*128 + k0 + acol;
            uint4 h0 = *(const uint4*)(g_qkhi + src);
            uint4 h1 = *(const uint4*)(g_qkhi + src + 8);
            uint4 l0 = *(const uint4*)(g_qklo + src);
            uint4 l1 = *(const uint4*)(g_qklo + src + 8);
            __syncthreads();
            *(uint4*)&sAhi[arow][acol]     = h0;
            *(uint4*)&sAhi[arow][acol + 8] = h1;
            *(uint4*)&sAlo[arow][acol]     = l0;
            *(uint4*)&sAlo[arow][acol + 8] = l1;
        }
        if (tid < EROWS*2) {
            const int brow = tid >> 1;
            const int bcol = (tid & 1) * 16;
            const size_t src = (size_t)brow*128 + k0 + bcol;
            *(uint4*)&sBhi[brow][bcol]     = *(const uint4*)(g_ehi + src);
            *(uint4*)&sBhi[brow][bcol + 8] = *(const uint4*)(g_ehi + src + 8);
            *(uint4*)&sBlo[brow][bcol]     = *(const uint4*)(g_elo + src);
            *(uint4*)&sBlo[brow][bcol + 8] = *(const uint4*)(g_elo + src + 8);
        }
        __syncthreads();

        #pragma unroll
        for (int ks = 0; ks < 2; ks++) {
            const uint32_t ko = ks * 32;
            uint32_t ah[4], al[4];
            ldsm_x4(aHi + ko, ah[0], ah[1], ah[2], ah[3]);
            ldsm_x4(aLo + ko, al[0], al[1], al[2], al[3]);
            #pragma unroll
            for (int pr = 0; pr < 7; pr++) {
                const uint32_t po = pr * (16 * LDSB * 2);
                uint32_t bhf[4], blf[4];
                ldsm_x4(bHi + po + ko, bhf[0], bhf[1], bhf[2], bhf[3]);
                ldsm_x4(bLo + po + ko, blf[0], blf[1], blf[2], blf[3]);
                #pragma unroll
                for (int h2 = 0; h2 < 2; h2++) {
                    const int nt = pr*2 + h2;
                    mma16816(acc[nt], ah, bhf[h2*2], bhf[h2*2+1]);
                    mma16816(acc[nt], ah, blf[h2*2], blf[h2*2+1]);
                    mma16816(acc[nt], al, bhf[h2*2], bhf[h2*2+1]);
                }
            }
        }
        __syncthreads();
    }

    const int gid = lane >> 2, tig = lane & 3;
    const int row0 = rt*128 + warp*16 + gid;
    #pragma unroll
    for (int nt = 0; nt < 14; nt++) {
        const int col = nt*8 + tig*2;
        #pragma unroll
        for (int half = 0; half < 2; half++) {
            const int row = row0 + half*8;
            const size_t o = (bh*S_ + row)*NRELV;
            const float v0 = acc[nt][half*2];
            const float v1 = acc[nt][half*2+1];
            if (col < NRELV)     g_bias[o + col]     = v0;
            if (col + 1 < NRELV) g_bias[o + col + 1] = v1;
        }
    }
}

// ---------------- fused attention: QT=32, cp.async double-buffered KV -----------
#define QT    32
#define SSTR  520
#define OFF_SS    0                        // 32*520*4 = 66560
#define KVHI(bf)  (66560u + (uint32_t)(bf)*36864u)   // each buf: hi 18432 + lo 18432
#define KVLO(bf)  (84992u + (uint32_t)(bf)*36864u)
#define OFF_EV    66560                    // Ev fp32 (reuses KV buf0 after PV)
#define OFF_SB    140288                   // 32*101*4 = 12928
#define OFF_SW    153216                   // 12928
#define OFF_SZ    166144                   // 128
#define OFF_MASK  166272                   // 2048
#define SMEM_ATTN 168320

__global__ void __launch_bounds__(512, 1)
attn_kernel(const int* __restrict__ mask, const float* __restrict__ Ev)
{
    extern __shared__ char smraw[];
    const uint32_t sbase = (uint32_t)__cvta_generic_to_shared(smraw);
    float* sS    = (float*)(smraw + OFF_SS);
    float* sEv   = (float*)(smraw + OFF_EV);
    float* sB    = (float*)(smraw + OFF_SB);
    float* sW    = (float*)(smraw + OFF_SW);
    float* sZ    = (float*)(smraw + OFF_SZ);
    int*   sMask = (int*)  (smraw + OFF_MASK);

    const int qt = blockIdx.x, h = blockIdx.y, b = blockIdx.z;
    const int i0 = qt * QT;
    const int tid  = threadIdx.x;
    const int lane = tid & 31;
    const int warp = tid >> 5;        // 0..15
    const int mt   = warp >> 3;       // m-tile 0/1
    const int wj   = warp & 7;        // j-slice
    const size_t bh    = (size_t)b*H_ + h;
    const size_t qrow0 = bh*S_ + i0;
    const size_t krow0 = bh*S_;
    const size_t vbase = bh*S_*HD_;

    const int copyrow = tid >> 2;           // 0..127
    const int cq      = (tid & 3) * 16;     // element offset within 64-wide row
    const uint32_t dOff = (uint32_t)(copyrow*144 + cq*2);   // 144 = 9*16, 16B-aligned

    // ---- issue K tile 0 into buf0 immediately ----
    {
        const size_t src = (krow0 + copyrow)*128 + 64 + cq;
        cp16(sbase + KVHI(0) + dOff,      g_qkhi + src);
        cp16(sbase + KVHI(0) + dOff + 16, g_qkhi + src + 8);
        cp16(sbase + KVLO(0) + dOff,      g_qklo + src);
        cp16(sbase + KVLO(0) + dOff + 16, g_qklo + src + 8);
    }
    asm volatile("cp.async.commit_group;");

    for (int i = tid; i < QT*NRELV; i += 512) {
        sB[i] = g_bias[qrow0*NRELV + i];
        sW[i] = 0.f;
    }
    for (int i = tid; i < S_; i += 512) sMask[i] = mask[b*S_ + i];

    // ---- Q A-fragments (global loads, overlap with K0 copy) ----
    uint32_t qah[4][4], qal[4][4];
    {
        const int qr = lane >> 2;
        const int qc = (lane & 3) * 2;
        const size_t qm = qrow0 + mt*16;
        #pragma unroll
        for (int kk = 0; kk < 4; kk++) {
            const size_t r0o = (qm + qr)*128     + kk*16 + qc;
            const size_t r1o = (qm + qr + 8)*128 + kk*16 + qc;
            qah[kk][0] = *(const uint32_t*)&g_qkhi[r0o];
            qah[kk][1] = *(const uint32_t*)&g_qkhi[r1o];
            qah[kk][2] = *(const uint32_t*)&g_qkhi[r0o + 8];
            qah[kk][3] = *(const uint32_t*)&g_qkhi[r1o + 8];
            qal[kk][0] = *(const uint32_t*)&g_qklo[r0o];
            qal[kk][1] = *(const uint32_t*)&g_qklo[r1o];
            qal[kk][2] = *(const uint32_t*)&g_qklo[r0o + 8];
            qal[kk][3] = *(const uint32_t*)&g_qklo[r1o + 8];
        }
    }
    __syncthreads();

    // ---- pass 1: S = Q K^T, double-buffered ----
    for (int jt = 0; jt < 4; jt++) {
        // prefetch next K tile (or V tile 0) into the other buffer
        if (jt < 3) {
            const int nb = (jt + 1) & 1;
            const size_t src = (krow0 + (jt+1)*128 + copyrow)*128 + 64 + cq;
            cp16(sbase + KVHI(nb) + dOff,      g_qkhi + src);
            cp16(sbase + KVHI(nb) + dOff + 16, g_qkhi + src + 8);
            cp16(sbase + KVLO(nb) + dOff,      g_qklo + src);
            cp16(sbase + KVLO(nb) + dOff + 16, g_qklo + src + 8);
        } else {
            const size_t src = vbase + (size_t)copyrow*HD_ + cq;
            cp16(sbase + KVHI(0) + dOff,      g_vhi + src);
            cp16(sbase + KVHI(0) + dOff + 16, g_vhi + src + 8);
            cp16(sbase + KVLO(0) + dOff,      g_vlo + src);
            cp16(sbase + KVLO(0) + dOff + 16, g_vlo + src + 8);
        }
        asm volatile("cp.async.commit_group;");
        asm volatile("cp.async.wait_group 1;");
        __syncthreads();

        const __nv_bfloat16* kh = (const __nv_bfloat16*)(smraw + KVHI(jt & 1));
        const __nv_bfloat16* kl = (const __nv_bfloat16*)(smraw + KVLO(jt & 1));
        const int j0 = jt * 128;

        float c[2][4] = {{0,0,0,0},{0,0,0,0}};
        const int nw = wj * 16;
        #pragma unroll
        for (int kk = 0; kk < 4; kk++) {
            #pragma unroll
            for (int nt = 0; nt < 2; nt++) {
                const int j = nw + nt*8 + (lane >> 2);
                const int d = kk*16 + (lane & 3)*2;
                uint32_t bh0 = *(uint32_t*)&kh[j*72 + d];
                uint32_t bh1 = *(uint32_t*)&kh[j*72 + d + 8];
                uint32_t bl0 = *(uint32_t*)&kl[j*72 + d];
                uint32_t bl1 = *(uint32_t*)&kl[j*72 + d + 8];
                mma16816(c[nt], qah[kk], bh0, bh1);
                mma16816(c[nt], qah[kk], bl0, bl1);
                mma16816(c[nt], qal[kk], bh0, bh1);
            }
        }
        #pragma unroll
        for (int nt = 0; nt < 2; nt++) {
            const int col = j0 + nw + nt*8 + 2*(lane & 3);
            const int r   = mt*16 + (lane >> 2);
            *(float2*)&sS[r*SSTR + col]     = make_float2(c[nt][0], c[nt][1]);
            *(float2*)&sS[(r+8)*SSTR + col] = make_float2(c[nt][2], c[nt][3]);
        }
        __syncthreads();
    }

    // prefetch V tile 1 into buf1 (buf1 last read at jt=3, synced)
    {
        const size_t src = vbase + (size_t)(128 + copyrow)*HD_ + cq;
        cp16(sbase + KVHI(1) + dOff,      g_vhi + src);
        cp16(sbase + KVHI(1) + dOff + 16, g_vhi + src + 8);
        cp16(sbase + KVLO(1) + dOff,      g_vlo + src);
        cp16(sbase + KVLO(1) + dOff + 16, g_vlo + src + 8);
    }
    asm volatile("cp.async.commit_group;");

    // ---- relation bias + scale + mask (overlaps V0/V1 copies) ----
    const size_t arcbase = ((size_t)b*S_ + i0)*S_;
    for (int idx4 = tid; idx4 < QT*S_/4; idx4 += 512) {
        const int idx = idx4 * 4;
        const int i = idx >> 9, j = idx & (S_-1);
        uchar4 r4 = *(const uchar4*)&g_rel8[arcbase + (size_t)i*S_ + j];
        const float* brow = &sB[i*NRELV];
        float4 s4 = *(float4*)&sS[i*SSTR + j];
        s4.x = (s4.x + brow[r4.x]) * 0.125f; if (sMask[j]     == 0) s4.x = -1e30f;
        s4.y = (s4.y + brow[r4.y]) * 0.125f; if (sMask[j + 1] == 0) s4.y = -1e30f;
        s4.z = (s4.z + brow[r4.z]) * 0.125f; if (sMask[j + 2] == 0) s4.z = -1e30f;
        s4.w = (s4.w + brow[r4.w]) * 0.125f; if (sMask[j + 3] == 0) s4.w = -1e30f;
        *(float4*)&sS[i*SSTR + j] = s4;
    }
    __syncthreads();

    // ---- softmax ----
    #pragma unroll
    for (int rr = 0; rr < 2; rr++) {
        int row = warp*2 + rr;
        float m = -3.4e38f;
        for (int j = lane; j < S_; j += 32) m = fmaxf(m, sS[row*SSTR + j]);
        #pragma unroll
        for (int o = 16; o; o >>= 1) m = fmaxf(m, __shfl_xor_sync(0xffffffffu, m, o));
        float z = 0.f;
        for (int j = lane; j < S_; j += 32) {
            float p = __expf(sS[row*SSTR + j] - m);
            sS[row*SSTR + j] = p;
            z += p;
        }
        #pragma unroll
        for (int o = 16; o; o >>= 1) z += __shfl_xor_sync(0xffffffffu, z, o);
        if (lane == 0) sZ[row] = z;
    }
    __syncthreads();

    // ---- relation binning ----
    for (int idx4 = tid; idx4 < QT*S_/4; idx4 += 512) {
        const int idx = idx4 * 4;
        const int i = idx >> 9, j = idx & (S_-1);
        uchar4 r4 = *(const uchar4*)&g_rel8[arcbase + (size_t)i*S_ + j];
        float4 p4 = *(float4*)&sS[i*SSTR + j];
        float* wrow = &sW[i*NRELV];
        atomicAdd(&wrow[r4.x], p4.x);
        atomicAdd(&wrow[r4.y], p4.y);
        atomicAdd(&wrow[r4.z], p4.z);
        atomicAdd(&wrow[r4.w], p4.w);
    }
    __syncthreads();

    // ---- pass 2: ctx = P V, double-buffered ----
    float c2[8][4];
    #pragma unroll
    for (int nt = 0; nt < 8; nt++)
        #pragma unroll
        for (int j = 0; j < 4; j++) c2[nt][j] = 0.f;

    for (int jt = 0; jt < 4; jt++) {
        if (jt < 3) { asm volatile("cp.async.wait_group 1;"); }
        else        { asm volatile("cp.async.wait_group 0;"); }
        __syncthreads();

        const uint32_t vh = sbase + KVHI(jt & 1);
        const uint32_t vl = sbase + KVLO(jt & 1);
        const int jb = jt*128 + wj*16;
        uint32_t pah[4], pal[4];
        {
            const int pr = mt*16 + (lane >> 2);
            const int pc = (lane & 3) * 2;
            float2 x0 = *(float2*)&sS[pr*SSTR     + jb + pc];
            float2 x1 = *(float2*)&sS[(pr+8)*SSTR + jb + pc];
            float2 x2 = *(float2*)&sS[pr*SSTR     + jb + pc + 8];
            float2 x3 = *(float2*)&sS[(pr+8)*SSTR + jb + pc + 8];
            split2(x0.x, x0.y, pah[0], pal[0]);
            split2(x1.x, x1.y, pah[1], pal[1]);
            split2(x2.x, x2.y, pah[2], pal[2]);
            split2(x3.x, x3.y, pah[3], pal[3]);
        }
        const uint32_t rowoff = (uint32_t)(wj*16 + (lane & 15)) * 144;
        #pragma unroll
        for (int nt = 0; nt < 8; nt++) {
            uint32_t bh0, bh1, bl0, bl1;
            ldsm_x2_trans(vh + rowoff + nt*16, bh0, bh1);
            ldsm_x2_trans(vl + rowoff + nt*16, bl0, bl1);
            mma16816(c2[nt], pah, bh0, bh1);
            mma16816(c2[nt], pah, bl0, bl1);
            mma16816(c2[nt], pal, bh0, bh1);
        }
        __syncthreads();

        if (jt + 2 < 4) {
            const int nb = jt & 1;
            const size_t src = vbase + (size_t)((jt+2)*128 + copyrow)*HD_ + cq;
            cp16(sbase + KVHI(nb) + dOff,      g_vhi + src);
            cp16(sbase + KVHI(nb) + dOff + 16, g_vhi + src + 8);
            cp16(sbase + KVLO(nb) + dOff,      g_vlo + src);
            cp16(sbase + KVLO(nb) + dOff + 16, g_vlo + src + 8);
            asm volatile("cp.async.commit_group;");
        }
    }

    // ---- PV partials to smem (reuse sS) + load Ev (into KV buf0 region) ----
    {
        float* red = sS;
        const int r = lane >> 2;
        #pragma unroll
        for (int nt = 0; nt < 8; nt++) {
            const int col = nt*8 + 2*(lane & 3);
            red[warp*1024 + r*64 + col]       = c2[nt][0];
            red[warp*1024 + r*64 + col + 1]   = c2[nt][1];
            red[warp*1024 + (r+8)*64 + col]   = c2[nt][2];
            red[warp*1024 + (r+8)*64 + col+1] = c2[nt][3];
        }
    }
    for (int i = tid; i < NRELV*HD_; i += 512) sEv[i] = Ev[i];
    __syncthreads();

    // ---- final: reduce 8 partials, + wrel@Ev, /Z, store ctx hi/lo ----
    {
        const int row = tid >> 4;            // 0..31
        const int e0  = (tid & 15) * 4;
        const int rmt = row >> 4, rl = row & 15;
        float4 acc = make_float4(0,0,0,0);
        #pragma unroll
        for (int w = 0; w < 8; w++) {
            float4 p = *(float4*)&sS[(rmt*8 + w)*1024 + rl*64 + e0];
            acc.x += p.x; acc.y += p.y; acc.z += p.z; acc.w += p.w;
        }
        const float* wrow = &sW[row*NRELV];
        for (int rel = 0; rel < NRELV; rel++) {
            float wv = wrow[rel];
            float4 ev = *(float4*)&sEv[rel*64 + e0];
            acc.x += wv*ev.x; acc.y += wv*ev.y; acc.z += wv*ev.z; acc.w += wv*ev.w;
        }
        const float rz = 1.f / sZ[row];
        acc.x *= rz; acc.y *= rz; acc.z *= rz; acc.w *= rz;

        uint32_t h0, l0, h1, l1;
        split2(acc.x, acc.y, h0, l0);
        split2(acc.z, acc.w, h1, l1);
        const size_t o = ((size_t)(b*S_ + i0 + row))*D_ + h*HD_ + e0;
        *(uint2*)&g_chi[o] = make_uint2(h0, h1);
        *(uint2*)&g_clo[o] = make_uint2(l0, l1);
    }
}

// ---------------- launch --------------------------------------------------------
extern "C" void kernel_launch(void* const* d_in, const int* in_sizes, int n_in,
                              void* d_out, int out_size)
{
    (void)in_sizes; (void)n_in; (void)out_size;
    const float* query = (const float*)d_in[0];
    const float* key_  = (const float*)d_in[1];
    const float* value = (const float*)d_in[2];
    const int*   mask  = (const int*)d_in[3];
    const void*  arc   = d_in[4];
    const float* bq = (const float*)d_in[6];
    const float* bk = (const float*)d_in[8];
    const float* bv = (const float*)d_in[10];
    const float* bo = (const float*)d_in[12];
    const float* Ek = (const float*)d_in[13];
    const float* Eq = (const float*)d_in[14];
    const float* Ev = (const float*)d_in[15];
    float* out = (float*)d_out;

    cudaFuncSetAttribute(attn_kernel, cudaFuncAttributeMaxDynamicSharedMemorySize, SMEM_ATTN);
    cudaFuncSetAttribute(mma_gemm_kernel<0>, cudaFuncAttributeMaxDynamicSharedMemorySize, 2*GSTAGE);
    cudaFuncSetAttribute(mma_gemm_kernel<1>, cudaFuncAttributeMaxDynamicSharedMemorySize, 2*GSTAGE);

    __nv_bfloat16 *xhi, *xlo, *whi, *wlo;
    cudaGetSymbolAddress((void**)&xhi, g_xhi);
    cudaGetSymbolAddress((void**)&xlo, g_xlo);
    cudaGetSymbolAddress((void**)&whi, g_whi);
    cudaGetSymbolAddress((void**)&wlo, g_wlo);

    detect_kernel<<<1, 256>>>((const int*)arc);
    rel8_kernel<<<((B_*S_*S_/4) + 255)/256, 256>>>(arc);

    SplitArgs sa;
    const float* srcs[7] = {query, key_, value,
                            (const float*)d_in[5], (const float*)d_in[7],
                            (const float*)d_in[9], (const float*)d_in[11]};
    for (int i = 0; i < 7; i++) {
        sa.src[i] = srcs[i];
        if (i < 3) {
            sa.hi[i] = xhi + (size_t)i*XN;
            sa.lo[i] = xlo + (size_t)i*XN;
            sa.n[i]  = XN;
        } else {
            sa.hi[i] = whi + (size_t)(i-3)*WN;
            sa.lo[i] = wlo + (size_t)(i-3)*WN;
            sa.n[i]  = WN;
        }
    }
    split_kernel<<<dim3((XN/4 + 255)/256, 7), 256>>>(sa);
    ebuild_kernel<<<(EROWS*128 + 255)/256, 256>>>(Ek, Eq);

    dim3 qkvGrid(D_/BN, (B_*S_)/BM, 3);
    mma_gemm_kernel<0><<<qkvGrid, 256, 2*GSTAGE>>>(bq, bk, bv, nullptr);

    bias_mma_kernel<<<dim3(4, H_, B_), 256>>>();
    attn_kernel<<<dim3(S_/QT, H_, B_), 512, SMEM_ATTN>>>(mask, Ev);

    dim3 oGrid(D_/BN, (B_*S_)/BM, 1);
    mma_gemm_kernel<1><<<oGrid, 256, 2*GSTAGE>>>(bo, nullptr, nullptr, out);
}

// round 11
// speedup vs baseline: 1.1826x; 1.0715x over previous
#include <cuda_runtime.h>
#include <cuda_bf16.h>
#include <cstdint>
#include <cstddef>

#define B_    4
#define S_    512
#define D_    768
#define H_    12
#define HD_   64
#define NRELV 101
#define EROWS 112
#define XN    (B_*S_*D_)
#define WN    (D_*D_)

#define BM    128
#define BN    128
#define BK    32
#define LDSB  40           // bf16 stride (80B) -> ldmatrix conflict-free
#define GSTAGE 40960       // bytes per gemm pipeline stage

// ---------------- scratch ------------------------------------------------------
__device__ __nv_bfloat16 g_qkhi[(size_t)B_*H_*S_*128], g_qklo[(size_t)B_*H_*S_*128];
__device__ __nv_bfloat16 g_vhi[XN], g_vlo[XN];
__device__ __nv_bfloat16 g_xhi[3*XN], g_xlo[3*XN];
__device__ __nv_bfloat16 g_whi[4*WN], g_wlo[4*WN];
__device__ __nv_bfloat16 g_chi[XN], g_clo[XN];
__device__ __nv_bfloat16 g_ehi[EROWS*128], g_elo[EROWS*128];
__device__ float   g_bias[(size_t)B_*H_*S_*NRELV];
__device__ uint8_t g_rel8[(size_t)B_*S_*S_];
__device__ int     g_arc_is64;

// ---------------- helpers ------------------------------------------------------
__device__ __forceinline__ void split2(float a, float b, uint32_t& hi, uint32_t& lo)
{
    __nv_bfloat16 h0 = __float2bfloat16(a);
    __nv_bfloat16 h1 = __float2bfloat16(b);
    __nv_bfloat16 l0 = __float2bfloat16(a - __bfloat162float(h0));
    __nv_bfloat16 l1 = __float2bfloat16(b - __bfloat162float(h1));
    hi = (uint32_t)*(unsigned short*)&h0 | ((uint32_t)*(unsigned short*)&h1 << 16);
    lo = (uint32_t)*(unsigned short*)&l0 | ((uint32_t)*(unsigned short*)&l1 << 16);
}

__device__ __forceinline__ void ldsm_x4(uint32_t addr, uint32_t& r0, uint32_t& r1,
                                        uint32_t& r2, uint32_t& r3)
{
    asm volatile("ldmatrix.sync.aligned.m8n8.x4.shared.b16 {%0,%1,%2,%3}, [%4];"
                 : "=r"(r0), "=r"(r1), "=r"(r2), "=r"(r3) : "r"(addr));
}

__device__ __forceinline__ void ldsm_x2_trans(uint32_t addr, uint32_t& r0, uint32_t& r1)
{
    asm volatile("ldmatrix.sync.aligned.m8n8.x2.trans.shared.b16 {%0,%1}, [%2];"
                 : "=r"(r0), "=r"(r1) : "r"(addr));
}

__device__ __forceinline__ void mma16816(float* c, const uint32_t* a,
                                         uint32_t b0, uint32_t b1)
{
    asm volatile(
        "mma.sync.aligned.m16n8k16.row.col.f32.bf16.bf16.f32 "
        "{%0,%1,%2,%3}, {%4,%5,%6,%7}, {%8,%9}, {%0,%1,%2,%3};"
        : "+f"(c[0]), "+f"(c[1]), "+f"(c[2]), "+f"(c[3])
        : "r"(a[0]), "r"(a[1]), "r"(a[2]), "r"(a[3]), "r"(b0), "r"(b1));
}

__device__ __forceinline__ void cp16(uint32_t dst, const void* src)
{
    asm volatile("cp.async.ca.shared.global [%0], [%1], 16;" :: "r"(dst), "l"(src));
}

// ---------------- graph_arc dtype detection ------------------------------------
__global__ void detect_kernel(const int* __restrict__ arc32)
{
    __shared__ int cnt;
    if (threadIdx.x == 0) cnt = 0;
    __syncthreads();
    int local = 0;
    for (int i = threadIdx.x; i < 1024; i += blockDim.x)
        if (arc32[2*i + 1] != 0) local++;
    if (local) atomicAdd(&cnt, local);
    __syncthreads();
    if (threadIdx.x == 0) g_arc_is64 = (cnt == 0) ? 1 : 0;
}

// arc (int32 or int64) -> uint8 relation table
__global__ void __launch_bounds__(256)
rel8_kernel(const void* __restrict__ arc)
{
    const int is64 = g_arc_is64;
    const size_t i = ((size_t)blockIdx.x * 256 + threadIdx.x) * 4;
    if (i >= (size_t)B_*S_*S_) return;
    uchar4 r;
    if (is64) {
        const long long* a = (const long long*)arc + i;
        r = make_uchar4((uint8_t)a[0], (uint8_t)a[1], (uint8_t)a[2], (uint8_t)a[3]);
    } else {
        const int* a = (const int*)arc + i;
        r = make_uchar4((uint8_t)a[0], (uint8_t)a[1], (uint8_t)a[2], (uint8_t)a[3]);
    }
    *(uchar4*)&g_rel8[i] = r;
}

// ---------------- prepass: fp32 -> bf16 hi/lo split -----------------------------
struct SplitArgs {
    const float*   src[7];
    __nv_bfloat16* hi[7];
    __nv_bfloat16* lo[7];
    int            n[7];
};

__global__ void __launch_bounds__(256)
split_kernel(SplitArgs a)
{
    const int w = blockIdx.y;
    const int n = a.n[w];
    const int i = (blockIdx.x * 256 + threadIdx.x) * 4;
    if (i >= n) return;
    float4 v = *(const float4*)(a.src[w] + i);
    uint32_t h0, l0, h1, l1;
    split2(v.x, v.y, h0, l0);
    split2(v.z, v.w, h1, l1);
    *(uint2*)(a.hi[w] + i) = make_uint2(h0, h1);
    *(uint2*)(a.lo[w] + i) = make_uint2(l0, l1);
}

__global__ void __launch_bounds__(256)
ebuild_kernel(const float* __restrict__ Ek, const float* __restrict__ Eq)
{
    int idx = blockIdx.x * 256 + threadIdx.x;
    if (idx >= EROWS*128) return;
    int row = idx >> 7, col = idx & 127;
    float v = 0.f;
    if (row < NRELV) v = (col < 64) ? Ek[row*64 + col] : Eq[row*64 + col - 64];
    __nv_bfloat16 hv = __float2bfloat16(v);
    __nv_bfloat16 lv = __float2bfloat16(v - __bfloat162float(hv));
    g_ehi[idx] = hv;
    g_elo[idx] = lv;
}

// ---------------- tensor-core GEMM, cp.async 2-stage pipeline -------------------
template<int MODE>
__global__ void __launch_bounds__(256, 2)
mma_gemm_kernel(const float* __restrict__ bias0, const float* __restrict__ bias1,
                const float* __restrict__ bias2, float* __restrict__ out1)
{
    extern __shared__ char gsm[];
    const uint32_t smemBase = (uint32_t)__cvta_generic_to_shared(gsm);

    const int z = (MODE == 0) ? blockIdx.z : 0;
    const __nv_bfloat16 *Xhi, *Xlo, *Whi, *Wlo;
    const float* bias;
    if (MODE == 0) {
        Xhi = g_xhi + (size_t)z*XN;  Xlo = g_xlo + (size_t)z*XN;
        Whi = g_whi + (size_t)z*WN;  Wlo = g_wlo + (size_t)z*WN;
        bias = (z == 0) ? bias0 : (z == 1) ? bias1 : bias2;
    } else {
        Xhi = g_chi;  Xlo = g_clo;
        Whi = g_whi + (size_t)3*WN;  Wlo = g_wlo + (size_t)3*WN;
        bias = bias0;
    }

    const int tid  = threadIdx.x;
    const int lane = tid & 31;
    const int warp = tid >> 5;
    const int wm   = warp & 3;
    const int wn   = warp >> 2;
    const int m0   = blockIdx.y * BM;
    const int n0   = blockIdx.x * BN;

    float acc[2][8][4];
    #pragma unroll
    for (int mt = 0; mt < 2; mt++)
        #pragma unroll
        for (int nt = 0; nt < 8; nt++)
            #pragma unroll
            for (int j = 0; j < 4; j++) acc[mt][nt][j] = 0.f;

    const int mat = lane >> 3, mr = lane & 7;
    const uint32_t aOffHi = (uint32_t)((wm*32 + (mat & 1)*8 + mr)*80 + ((mat >> 1)*8)*2);
    const uint32_t bOffHi = 20480u + (uint32_t)((wn*64 + (mat >> 1)*8 + mr)*80 + ((mat & 1)*8)*2);

    const int ldrow = tid >> 1;
    const int ldq   = (tid & 1) * 2;
    const uint32_t xDst = (uint32_t)(ldrow*80 + ldq*16);
    const uint32_t wDst = 20480u + xDst;

    #pragma unroll
    for (int u = 0; u < 2; u++) {
        const size_t xo = (size_t)(m0 + ldrow)*D_ + (ldq + u)*8;
        const size_t wo = (size_t)(n0 + ldrow)*D_ + (ldq + u)*8;
        cp16(smemBase + xDst + u*16,          Xhi + xo);
        cp16(smemBase + 10240 + xDst + u*16,  Xlo + xo);
        cp16(smemBase + wDst + u*16,          Whi + wo);
        cp16(smemBase + 10240 + wDst + u*16,  Wlo + wo);
    }
    asm volatile("cp.async.commit_group;");

    const int NK = D_ / BK;
    for (int kt = 0; kt < NK; kt++) {
        asm volatile("cp.async.wait_group 0;");
        __syncthreads();

        if (kt + 1 < NK) {
            const uint32_t sb2 = smemBase + (uint32_t)(((kt + 1) & 1) * GSTAGE);
            const int k0 = (kt + 1) * BK;
            #pragma unroll
            for (int u = 0; u < 2; u++) {
                const size_t xo = (size_t)(m0 + ldrow)*D_ + k0 + (ldq + u)*8;
                const size_t wo = (size_t)(n0 + ldrow)*D_ + k0 + (ldq + u)*8;
                cp16(sb2 + xDst + u*16,          Xhi + xo);
                cp16(sb2 + 10240 + xDst + u*16,  Xlo + xo);
                cp16(sb2 + wDst + u*16,          Whi + wo);
                cp16(sb2 + 10240 + wDst + u*16,  Wlo + wo);
            }
        }
        asm volatile("cp.async.commit_group;");

        const uint32_t sb = smemBase + (uint32_t)((kt & 1) * GSTAGE);
        #pragma unroll
        for (int ks = 0; ks < 2; ks++) {
            const uint32_t ko = ks * 32;
            uint32_t ah[2][4], al[2][4];
            #pragma unroll
            for (int mt = 0; mt < 2; mt++) {
                const uint32_t mo = mt * 1280;
                ldsm_x4(sb + aOffHi + mo + ko,          ah[mt][0], ah[mt][1], ah[mt][2], ah[mt][3]);
                ldsm_x4(sb + aOffHi + 10240 + mo + ko,  al[mt][0], al[mt][1], al[mt][2], al[mt][3]);
            }
            #pragma unroll
            for (int pr = 0; pr < 4; pr++) {
                const uint32_t po = pr * 1280;
                uint32_t bh[4], bl[4];
                ldsm_x4(sb + bOffHi + po + ko,          bh[0], bh[1], bh[2], bh[3]);
                ldsm_x4(sb + bOffHi + 10240 + po + ko,  bl[0], bl[1], bl[2], bl[3]);
                #pragma unroll
                for (int h2 = 0; h2 < 2; h2++) {
                    const int nt = pr*2 + h2;
                    #pragma unroll
                    for (int mt = 0; mt < 2; mt++) {
                        mma16816(acc[mt][nt], ah[mt], bh[h2*2], bh[h2*2+1]);
                        mma16816(acc[mt][nt], ah[mt], bl[h2*2], bl[h2*2+1]);
                        mma16816(acc[mt][nt], al[mt], bh[h2*2], bh[h2*2+1]);
                    }
                }
            }
        }
    }

    const int gid = lane >> 2, tig = lane & 3;
    #pragma unroll
    for (int mt = 0; mt < 2; mt++) {
        const int rbase = m0 + wm*32 + mt*16 + gid;
        #pragma unroll
        for (int nt = 0; nt < 8; nt++) {
            const int col = n0 + wn*64 + nt*8 + tig*2;
            const float b0v = bias[col], b1v = bias[col+1];
            float v00 = acc[mt][nt][0] + b0v;
            float v01 = acc[mt][nt][1] + b1v;
            float v10 = acc[mt][nt][2] + b0v;
            float v11 = acc[mt][nt][3] + b1v;
            if (MODE == 0) {
                const int hh = col >> 6, e = col & 63;
                #pragma unroll
                for (int half = 0; half < 2; half++) {
                    const int r = rbase + half*8;
                    const int b = r >> 9, s = r & (S_-1);
                    const size_t rowb = (size_t)(b*H_ + hh)*S_ + s;
                    const float va = half ? v10 : v00;
                    const float vb = half ? v11 : v01;
                    uint32_t hi, lo; split2(va, vb, hi, lo);
                    if (z == 0) {
                        *(uint32_t*)&g_qkhi[rowb*128 + e] = hi;
                        *(uint32_t*)&g_qklo[rowb*128 + e] = lo;
                    } else if (z == 1) {
                        *(uint32_t*)&g_qkhi[rowb*128 + 64 + e] = hi;
                        *(uint32_t*)&g_qklo[rowb*128 + 64 + e] = lo;
                    } else {
                        *(uint32_t*)&g_vhi[rowb*64 + e] = hi;
                        *(uint32_t*)&g_vlo[rowb*64 + e] = lo;
                    }
                }
            } else {
                out1[(size_t)rbase*D_ + col]       = v00;
                out1[(size_t)rbase*D_ + col + 1]   = v01;
                out1[(size_t)(rbase+8)*D_ + col]   = v10;
                out1[(size_t)(rbase+8)*D_ + col+1] = v11;
            }
        }
    }
}

// ---------------- bias table via tensor cores -----------------------------------
__global__ void __launch_bounds__(256, 1)
bias_mma_kernel()
{
    __shared__ __nv_bfloat16 sAhi[128][LDSB], sAlo[128][LDSB];
    __shared__ __nv_bfloat16 sBhi[EROWS][LDSB], sBlo[EROWS][LDSB];

    const int rt = blockIdx.x;
    const int h  = blockIdx.y, b = blockIdx.z;
    const size_t bh = (size_t)b*H_ + h;
    const size_t abase = (bh*S_ + rt*128) * 128;

    const int tid  = threadIdx.x;
    const int lane = tid & 31;
    const int warp = tid >> 5;

    float acc[14][4];
    #pragma unroll
    for (int nt = 0; nt < 14; nt++)
        #pragma unroll
        for (int j = 0; j < 4; j++) acc[nt][j] = 0.f;

    const int mat = lane >> 3, mr = lane & 7;
    const int a_row = (mat & 1) * 8 + mr;
    const int a_k   = (mat >> 1) * 8;
    const uint32_t aHi = (uint32_t)__cvta_generic_to_shared(&sAhi[warp*16 + a_row][a_k]);
    const uint32_t aLo = (uint32_t)__cvta_generic_to_shared(&sAlo[warp*16 + a_row][a_k]);
    const int b_row = (mat >> 1) * 8 + mr;
    const int b_k   = (mat & 1) * 8;
    const uint32_t bHi = (uint32_t)__cvta_generic_to_shared(&sBhi[b_row][b_k]);
    const uint32_t bLo = (uint32_t)__cvta_generic_to_shared(&sBlo[b_row][b_k]);

    for (int k0 = 0; k0 < 128; k0 += BK) {
        {
            const int arow = tid >> 1;
            const int acol = (tid & 1) * 16;
            const size_t src = abase + (size_t)arow*128 + k0 + acol;
            uint4 h0 = *(const uint4*)(g_qkhi + src);
            uint4 h1 = *(const uint4*)(g_qkhi + src + 8);
            uint4 l0 = *(const uint4*)(g_qklo + src);
            uint4 l1 = *(const uint4*)(g_qklo + src + 8);
            __syncthreads();
            *(uint4*)&sAhi[arow][acol]     = h0;
            *(uint4*)&sAhi[arow][acol + 8] = h1;
            *(uint4*)&sAlo[arow][acol]     = l0;
            *(uint4*)&sAlo[arow][acol + 8] = l1;
        }
        if (tid < EROWS*2) {
            const int brow = tid >> 1;
            const int bcol = (tid & 1) * 16;
            const size_t src = (size_t)brow*128 + k0 + bcol;
            *(uint4*)&sBhi[brow][bcol]     = *(const uint4*)(g_ehi + src);
            *(uint4*)&sBhi[brow][bcol + 8] = *(const uint4*)(g_ehi + src + 8);
            *(uint4*)&sBlo[brow][bcol]     = *(const uint4*)(g_elo + src);
            *(uint4*)&sBlo[brow][bcol + 8] = *(const uint4*)(g_elo + src + 8);
        }
        __syncthreads();

        #pragma unroll
        for (int ks = 0; ks < 2; ks++) {
            const uint32_t ko = ks * 32;
            uint32_t ah[4], al[4];
            ldsm_x4(aHi + ko, ah[0], ah[1], ah[2], ah[3]);
            ldsm_x4(aLo + ko, al[0], al[1], al[2], al[3]);
            #pragma unroll
            for (int pr = 0; pr < 7; pr++) {
                const uint32_t po = pr * (16 * LDSB * 2);
                uint32_t bhf[4], blf[4];
                ldsm_x4(bHi + po + ko, bhf[0], bhf[1], bhf[2], bhf[3]);
                ldsm_x4(bLo + po + ko, blf[0], blf[1], blf[2], blf[3]);
                #pragma unroll
                for (int h2 = 0; h2 < 2; h2++) {
                    const int nt = pr*2 + h2;
                    mma16816(acc[nt], ah, bhf[h2*2], bhf[h2*2+1]);
                    mma16816(acc[nt], ah, blf[h2*2], blf[h2*2+1]);
                    mma16816(acc[nt], al, bhf[h2*2], bhf[h2*2+1]);
                }
            }
        }
        __syncthreads();
    }

    const int gid = lane >> 2, tig = lane & 3;
    const int row0 = rt*128 + warp*16 + gid;
    #pragma unroll
    for (int nt = 0; nt < 14; nt++) {
        const int col = nt*8 + tig*2;
        #pragma unroll
        for (int half = 0; half < 2; half++) {
            const int row = row0 + half*8;
            const size_t o = (bh*S_ + row)*NRELV;
            const float v0 = acc[nt][half*2];
            const float v1 = acc[nt][half*2+1];
            if (col < NRELV)     g_bias[o + col]     = v0;
            if (col + 1 < NRELV) g_bias[o + col + 1] = v1;
        }
    }
}

// ---------------- fused attention: QT=32, cp.async KV, fused scalar phases ------
#define QT    32
#define SSTR  520
#define OFF_SS    0                        // 32*520*4 = 66560
#define KVHI(bf)  (66560u + (uint32_t)(bf)*36864u)
#define KVLO(bf)  (84992u + (uint32_t)(bf)*36864u)
#define OFF_SB    140288                   // 32*101*4 = 12928
#define OFF_SW    153216                   // 12928
#define OFF_SZ    166144                   // 128
#define OFF_MASK  166272                   // 2048
#define OFF_EV    168320                   // 101*64*4 = 25856 (dedicated)
#define SMEM_ATTN 194176

__global__ void __launch_bounds__(512, 1)
attn_kernel(const int* __restrict__ mask, const float* __restrict__ Ev)
{
    extern __shared__ char smraw[];
    const uint32_t sbase = (uint32_t)__cvta_generic_to_shared(smraw);
    float* sS    = (float*)(smraw + OFF_SS);
    float* sEv   = (float*)(smraw + OFF_EV);
    float* sB    = (float*)(smraw + OFF_SB);
    float* sW    = (float*)(smraw + OFF_SW);
    float* sZ    = (float*)(smraw + OFF_SZ);
    int*   sMask = (int*)  (smraw + OFF_MASK);

    const int qt = blockIdx.x, h = blockIdx.y, b = blockIdx.z;
    const int i0 = qt * QT;
    const int tid  = threadIdx.x;
    const int lane = tid & 31;
    const int warp = tid >> 5;        // 0..15
    const int mt   = warp >> 3;       // m-tile 0/1
    const int wj   = warp & 7;        // j-slice
    const size_t bh    = (size_t)b*H_ + h;
    const size_t qrow0 = bh*S_ + i0;
    const size_t krow0 = bh*S_;
    const size_t vbase = bh*S_*HD_;

    const int copyrow = tid >> 2;           // 0..127
    const int cq      = (tid & 3) * 16;     // element offset within 64-wide row
    const uint32_t dOff = (uint32_t)(copyrow*144 + cq*2);   // 144 = 9*16

    // ---- issue K tile 0 into buf0 immediately ----
    {
        const size_t src = (krow0 + copyrow)*128 + 64 + cq;
        cp16(sbase + KVHI(0) + dOff,      g_qkhi + src);
        cp16(sbase + KVHI(0) + dOff + 16, g_qkhi + src + 8);
        cp16(sbase + KVLO(0) + dOff,      g_qklo + src);
        cp16(sbase + KVLO(0) + dOff + 16, g_qklo + src + 8);
    }
    asm volatile("cp.async.commit_group;");

    for (int i = tid; i < QT*NRELV; i += 512) {
        sB[i] = g_bias[qrow0*NRELV + i];
        sW[i] = 0.f;
    }
    for (int i = tid; i < S_; i += 512) sMask[i] = mask[b*S_ + i];

    // ---- Q A-fragments (global loads, overlap with K0 copy) ----
    uint32_t qah[4][4], qal[4][4];
    {
        const int qr = lane >> 2;
        const int qc = (lane & 3) * 2;
        const size_t qm = qrow0 + mt*16;
        #pragma unroll
        for (int kk = 0; kk < 4; kk++) {
            const size_t r0o = (qm + qr)*128     + kk*16 + qc;
            const size_t r1o = (qm + qr + 8)*128 + kk*16 + qc;
            qah[kk][0] = *(const uint32_t*)&g_qkhi[r0o];
            qah[kk][1] = *(const uint32_t*)&g_qkhi[r1o];
            qah[kk][2] = *(const uint32_t*)&g_qkhi[r0o + 8];
            qah[kk][3] = *(const uint32_t*)&g_qkhi[r1o + 8];
            qal[kk][0] = *(const uint32_t*)&g_qklo[r0o];
            qal[kk][1] = *(const uint32_t*)&g_qklo[r1o];
            qal[kk][2] = *(const uint32_t*)&g_qklo[r0o + 8];
            qal[kk][3] = *(const uint32_t*)&g_qklo[r1o + 8];
        }
    }
    __syncthreads();

    // B-fragment ldmatrix lane offset: mat0=rows j0..7 @k, mat1=j0..7 @k+8,
    // mat2=j0+8..15 @k, mat3=j0+8..15 @k+8
    const uint32_t bfragOff =
        (uint32_t)((wj*16 + ((lane >> 4) & 1)*8 + (lane & 7))*144 + ((lane >> 3) & 1)*16);

    // ---- pass 1: S = Q K^T, double-buffered ----
    for (int jt = 0; jt < 4; jt++) {
        if (jt < 3) {
            const int nb = (jt + 1) & 1;
            const size_t src = (krow0 + (jt+1)*128 + copyrow)*128 + 64 + cq;
            cp16(sbase + KVHI(nb) + dOff,      g_qkhi + src);
            cp16(sbase + KVHI(nb) + dOff + 16, g_qkhi + src + 8);
            cp16(sbase + KVLO(nb) + dOff,      g_qklo + src);
            cp16(sbase + KVLO(nb) + dOff + 16, g_qklo + src + 8);
        } else {
            const size_t src = vbase + (size_t)copyrow*HD_ + cq;
            cp16(sbase + KVHI(0) + dOff,      g_vhi + src);
            cp16(sbase + KVHI(0) + dOff + 16, g_vhi + src + 8);
            cp16(sbase + KVLO(0) + dOff,      g_vlo + src);
            cp16(sbase + KVLO(0) + dOff + 16, g_vlo + src + 8);
        }
        asm volatile("cp.async.commit_group;");
        asm volatile("cp.async.wait_group 1;");
        __syncthreads();

        const uint32_t khA = sbase + KVHI(jt & 1) + bfragOff;
        const uint32_t klA = sbase + KVLO(jt & 1) + bfragOff;
        const int j0 = jt * 128;

        float c[2][4] = {{0,0,0,0},{0,0,0,0}};
        #pragma unroll
        for (int kk = 0; kk < 4; kk++) {
            uint32_t bhf[4], blf[4];
            ldsm_x4(khA + kk*32, bhf[0], bhf[1], bhf[2], bhf[3]);
            ldsm_x4(klA + kk*32, blf[0], blf[1], blf[2], blf[3]);
            mma16816(c[0], qah[kk], bhf[0], bhf[1]);
            mma16816(c[0], qah[kk], blf[0], blf[1]);
            mma16816(c[0], qal[kk], bhf[0], bhf[1]);
            mma16816(c[1], qah[kk], bhf[2], bhf[3]);
            mma16816(c[1], qah[kk], blf[2], blf[3]);
            mma16816(c[1], qal[kk], bhf[2], bhf[3]);
        }
        #pragma unroll
        for (int nt = 0; nt < 2; nt++) {
            const int col = j0 + wj*16 + nt*8 + 2*(lane & 3);
            const int r   = mt*16 + (lane >> 2);
            *(float2*)&sS[r*SSTR + col]     = make_float2(c[nt][0], c[nt][1]);
            *(float2*)&sS[(r+8)*SSTR + col] = make_float2(c[nt][2], c[nt][3]);
        }
        __syncthreads();
    }

    // prefetch V tile 1 into buf1
    {
        const size_t src = vbase + (size_t)(128 + copyrow)*HD_ + cq;
        cp16(sbase + KVHI(1) + dOff,      g_vhi + src);
        cp16(sbase + KVHI(1) + dOff + 16, g_vhi + src + 8);
        cp16(sbase + KVLO(1) + dOff,      g_vlo + src);
        cp16(sbase + KVLO(1) + dOff + 16, g_vlo + src + 8);
    }
    asm volatile("cp.async.commit_group;");

    // ---- load Ev into its dedicated buffer (overlaps scalar phase) ----
    for (int i = tid; i < NRELV*HD_; i += 512) sEv[i] = Ev[i];

    // ---- fused scalar phase: per-warp rows, NO intra-phase syncs ----
    // pass A: bias + scale + mask + row max ; pass B: exp + Z + binning
    const size_t arcbase = ((size_t)b*S_ + i0)*S_;
    {
        uchar4 relreg[2][4];
        #pragma unroll
        for (int rr = 0; rr < 2; rr++) {
            const int row = warp*2 + rr;
            const float* brow = &sB[row*NRELV];
            float m = -3.4e38f;
            #pragma unroll
            for (int it = 0; it < 4; it++) {
                const int j = it*128 + lane*4;
                uchar4 r4 = *(const uchar4*)&g_rel8[arcbase + (size_t)row*S_ + j];
                relreg[rr][it] = r4;
                float4 s4 = *(float4*)&sS[row*SSTR + j];
                s4.x = (s4.x + brow[r4.x]) * 0.125f; if (sMask[j]     == 0) s4.x = -1e30f;
                s4.y = (s4.y + brow[r4.y]) * 0.125f; if (sMask[j + 1] == 0) s4.y = -1e30f;
                s4.z = (s4.z + brow[r4.z]) * 0.125f; if (sMask[j + 2] == 0) s4.z = -1e30f;
                s4.w = (s4.w + brow[r4.w]) * 0.125f; if (sMask[j + 3] == 0) s4.w = -1e30f;
                *(float4*)&sS[row*SSTR + j] = s4;
                m = fmaxf(m, fmaxf(fmaxf(s4.x, s4.y), fmaxf(s4.z, s4.w)));
            }
            #pragma unroll
            for (int o = 16; o; o >>= 1) m = fmaxf(m, __shfl_xor_sync(0xffffffffu, m, o));

            float z = 0.f;
            float* wrow = &sW[row*NRELV];
            #pragma unroll
            for (int it = 0; it < 4; it++) {
                const int j = it*128 + lane*4;
                float4 s4 = *(float4*)&sS[row*SSTR + j];
                float4 p4;
                p4.x = __expf(s4.x - m);
                p4.y = __expf(s4.y - m);
                p4.z = __expf(s4.z - m);
                p4.w = __expf(s4.w - m);
                *(float4*)&sS[row*SSTR + j] = p4;
                z += p4.x + p4.y + p4.z + p4.w;
                uchar4 r4 = relreg[rr][it];
                atomicAdd(&wrow[r4.x], p4.x);
                atomicAdd(&wrow[r4.y], p4.y);
                atomicAdd(&wrow[r4.z], p4.z);
                atomicAdd(&wrow[r4.w], p4.w);
            }
            #pragma unroll
            for (int o = 16; o; o >>= 1) z += __shfl_xor_sync(0xffffffffu, z, o);
            if (lane == 0) sZ[row] = z;
        }
    }
    __syncthreads();

    // ---- pass 2: ctx = P V, double-buffered ----
    float c2[8][4];
    #pragma unroll
    for (int nt = 0; nt < 8; nt++)
        #pragma unroll
        for (int j = 0; j < 4; j++) c2[nt][j] = 0.f;

    for (int jt = 0; jt < 4; jt++) {
        if (jt < 3) { asm volatile("cp.async.wait_group 1;"); }
        else        { asm volatile("cp.async.wait_group 0;"); }
        __syncthreads();

        const uint32_t vh = sbase + KVHI(jt & 1);
        const uint32_t vl = sbase + KVLO(jt & 1);
        const int jb = jt*128 + wj*16;
        uint32_t pah[4], pal[4];
        {
            const int pr = mt*16 + (lane >> 2);
            const int pc = (lane & 3) * 2;
            float2 x0 = *(float2*)&sS[pr*SSTR     + jb + pc];
            float2 x1 = *(float2*)&sS[(pr+8)*SSTR + jb + pc];
            float2 x2 = *(float2*)&sS[pr*SSTR     + jb + pc + 8];
            float2 x3 = *(float2*)&sS[(pr+8)*SSTR + jb + pc + 8];
            split2(x0.x, x0.y, pah[0], pal[0]);
            split2(x1.x, x1.y, pah[1], pal[1]);
            split2(x2.x, x2.y, pah[2], pal[2]);
            split2(x3.x, x3.y, pah[3], pal[3]);
        }
        const uint32_t rowoff = (uint32_t)(wj*16 + (lane & 15)) * 144;
        #pragma unroll
        for (int nt = 0; nt < 8; nt++) {
            uint32_t bh0, bh1, bl0, bl1;
            ldsm_x2_trans(vh + rowoff + nt*16, bh0, bh1);
            ldsm_x2_trans(vl + rowoff + nt*16, bl0, bl1);
            mma16816(c2[nt], pah, bh0, bh1);
            mma16816(c2[nt], pah, bl0, bl1);
            mma16816(c2[nt], pal, bh0, bh1);
        }
        __syncthreads();

        if (jt + 2 < 4) {
            const int nb = jt & 1;
            const size_t src = vbase + (size_t)((jt+2)*128 + copyrow)*HD_ + cq;
            cp16(sbase + KVHI(nb) + dOff,      g_vhi + src);
            cp16(sbase + KVHI(nb) + dOff + 16, g_vhi + src + 8);
            cp16(sbase + KVLO(nb) + dOff,      g_vlo + src);
            cp16(sbase + KVLO(nb) + dOff + 16, g_vlo + src + 8);
            asm volatile("cp.async.commit_group;");
        }
    }

    // ---- PV partials to smem (reuse sS) ----
    {
        float* red = sS;
        const int r = lane >> 2;
        #pragma unroll
        for (int nt = 0; nt < 8; nt++) {
            const int col = nt*8 + 2*(lane & 3);
            red[warp*1024 + r*64 + col]       = c2[nt][0];
            red[warp*1024 + r*64 + col + 1]   = c2[nt][1];
            red[warp*1024 + (r+8)*64 + col]   = c2[nt][2];
            red[warp*1024 + (r+8)*64 + col+1] = c2[nt][3];
        }
    }
    __syncthreads();

    // ---- final: reduce 8 partials, + wrel@Ev, /Z, store ctx hi/lo ----
    {
        const int row = tid >> 4;            // 0..31
        const int e0  = (tid & 15) * 4;
        const int rmt = row >> 4, rl = row & 15;
        float4 acc = make_float4(0,0,0,0);
        #pragma unroll
        for (int w = 0; w < 8; w++) {
            float4 p = *(float4*)&sS[(rmt*8 + w)*1024 + rl*64 + e0];
            acc.x += p.x; acc.y += p.y; acc.z += p.z; acc.w += p.w;
        }
        const float* wrow = &sW[row*NRELV];
        for (int rel = 0; rel < NRELV; rel++) {
            float wv = wrow[rel];
            float4 ev = *(float4*)&sEv[rel*64 + e0];
            acc.x += wv*ev.x; acc.y += wv*ev.y; acc.z += wv*ev.z; acc.w += wv*ev.w;
        }
        const float rz = 1.f / sZ[row];
        acc.x *= rz; acc.y *= rz; acc.z *= rz; acc.w *= rz;

        uint32_t h0, l0, h1, l1;
        split2(acc.x, acc.y, h0, l0);
        split2(acc.z, acc.w, h1, l1);
        const size_t o = ((size_t)(b*S_ + i0 + row))*D_ + h*HD_ + e0;
        *(uint2*)&g_chi[o] = make_uint2(h0, h1);
        *(uint2*)&g_clo[o] = make_uint2(l0, l1);
    }
}

// ---------------- launch --------------------------------------------------------
extern "C" void kernel_launch(void* const* d_in, const int* in_sizes, int n_in,
                              void* d_out, int out_size)
{
    (void)in_sizes; (void)n_in; (void)out_size;
    const float* query = (const float*)d_in[0];
    const float* key_  = (const float*)d_in[1];
    const float* value = (const float*)d_in[2];
    const int*   mask  = (const int*)d_in[3];
    const void*  arc   = d_in[4];
    const float* bq = (const float*)d_in[6];
    const float* bk = (const float*)d_in[8];
    const float* bv = (const float*)d_in[10];
    const float* bo = (const float*)d_in[12];
    const float* Ek = (const float*)d_in[13];
    const float* Eq = (const float*)d_in[14];
    const float* Ev = (const float*)d_in[15];
    float* out = (float*)d_out;

    cudaFuncSetAttribute(attn_kernel, cudaFuncAttributeMaxDynamicSharedMemorySize, SMEM_ATTN);
    cudaFuncSetAttribute(mma_gemm_kernel<0>, cudaFuncAttributeMaxDynamicSharedMemorySize, 2*GSTAGE);
    cudaFuncSetAttribute(mma_gemm_kernel<1>, cudaFuncAttributeMaxDynamicSharedMemorySize, 2*GSTAGE);

    __nv_bfloat16 *xhi, *xlo, *whi, *wlo;
    cudaGetSymbolAddress((void**)&xhi, g_xhi);
    cudaGetSymbolAddress((void**)&xlo, g_xlo);
    cudaGetSymbolAddress((void**)&whi, g_whi);
    cudaGetSymbolAddress((void**)&wlo, g_wlo);

    detect_kernel<<<1, 256>>>((const int*)arc);
    rel8_kernel<<<((B_*S_*S_/4) + 255)/256, 256>>>(arc);

    SplitArgs sa;
    const float* srcs[7] = {query, key_, value,
                            (const float*)d_in[5], (const float*)d_in[7],
                            (const float*)d_in[9], (const float*)d_in[11]};
    for (int i = 0; i < 7; i++) {
        sa.src[i] = srcs[i];
        if (i < 3) {
            sa.hi[i] = xhi + (size_t)i*XN;
            sa.lo[i] = xlo + (size_t)i*XN;
            sa.n[i]  = XN;
        } else {
            sa.hi[i] = whi + (size_t)(i-3)*WN;
            sa.lo[i] = wlo + (size_t)(i-3)*WN;
            sa.n[i]  = WN;
        }
    }
    split_kernel<<<dim3((XN/4 + 255)/256, 7), 256>>>(sa);
    ebuild_kernel<<<(EROWS*128 + 255)/256, 256>>>(Ek, Eq);

    dim3 qkvGrid(D_/BN, (B_*S_)/BM, 3);
    mma_gemm_kernel<0><<<qkvGrid, 256, 2*GSTAGE>>>(bq, bk, bv, nullptr);

    bias_mma_kernel<<<dim3(4, H_, B_), 256>>>();
    attn_kernel<<<dim3(S_/QT, H_, B_), 512, SMEM_ATTN>>>(mask, Ev);

    dim3 oGrid(D_/BN, (B_*S_)/BM, 1);
    mma_gemm_kernel<1><<<oGrid, 256, 2*GSTAGE>>>(bo, nullptr, nullptr, out);
}